// round 12
// baseline (speedup 1.0000x reference)
#include <cuda_runtime.h>
#include <cuda_bf16.h>
#include <stdint.h>
#include <math.h>

// ---------------------------------------------------------------------------
// Problem constants
// ---------------------------------------------------------------------------
#define BB   64
#define SS   512
#define HID  256
#define NH   4
#define DH   64
#define MROWS (BB*SS)            // 32768
#define MAT   (MROWS*HID)        // 8388608
#define NROW  (BB*NH*SS)         // 131072
#define WSZ   (HID*HID)          // 65536

// ---------------------------------------------------------------------------
// Scratch (device globals; no allocation allowed)
// ---------------------------------------------------------------------------
__device__ float g_dm[MAT];
__device__ float g_dc[MAT];
__device__ float g_aq[NROW];
__device__ float g_ak[NROW];
__device__ __nv_bfloat16 g_xmh[MAT], g_xml[MAT];
__device__ __nv_bfloat16 g_xch[MAT], g_xcl[MAT];
__device__ __nv_bfloat16 g_cmh[MAT], g_cml[MAT];
__device__ __nv_bfloat16 g_cch[MAT], g_ccl[MAT];
__device__ __nv_bfloat16 g_wh[8*WSZ], g_wl[8*WSZ];
__device__ __nv_bfloat16 g_mqh[MAT], g_mql[MAT];
__device__ __nv_bfloat16 g_mkh[MAT], g_mkl[MAT];
__device__ __nv_bfloat16 g_mvh[MAT], g_mvl[MAT];
__device__ __nv_bfloat16 g_sqh[MAT], g_sql[MAT];
__device__ __nv_bfloat16 g_skh[MAT], g_skl[MAT];
__device__ __nv_bfloat16 g_cvh[MAT], g_cvl[MAT];

// ---------------------------------------------------------------------------
// Helpers
// ---------------------------------------------------------------------------
__device__ __forceinline__ uint32_t smem_u32(const void* p) {
    uint32_t a;
    asm("{ .reg .u64 t; cvta.to.shared.u64 t, %1; cvt.u32.u64 %0, t; }"
        : "=r"(a) : "l"(p));
    return a;
}

#define LDSM_X4(d, addr) \
    asm volatile("ldmatrix.sync.aligned.m8n8.x4.shared.b16 {%0,%1,%2,%3}, [%4];" \
        : "=r"((d)[0]), "=r"((d)[1]), "=r"((d)[2]), "=r"((d)[3]) : "r"(addr))

#define LDSM_X4_T(d, addr) \
    asm volatile("ldmatrix.sync.aligned.m8n8.x4.trans.shared.b16 {%0,%1,%2,%3}, [%4];" \
        : "=r"((d)[0]), "=r"((d)[1]), "=r"((d)[2]), "=r"((d)[3]) : "r"(addr))

#define MMA_BF16(c, a, b) \
    asm volatile("mma.sync.aligned.m16n8k16.row.col.f32.bf16.bf16.f32 " \
        "{%0,%1,%2,%3}, {%4,%5,%6,%7}, {%8,%9}, {%0,%1,%2,%3};" \
        : "+f"((c)[0]), "+f"((c)[1]), "+f"((c)[2]), "+f"((c)[3]) \
        : "r"((a)[0]), "r"((a)[1]), "r"((a)[2]), "r"((a)[3]), \
          "r"((b)[0]), "r"((b)[1]))

__device__ __forceinline__ void cp16(uint32_t saddr, const void* g) {
    asm volatile("cp.async.cg.shared.global [%0], [%1], 16;" :: "r"(saddr), "l"(g));
}
#define CP_COMMIT() asm volatile("cp.async.commit_group;")
template<int N> __device__ __forceinline__ void cp_wait() {
    asm volatile("cp.async.wait_group %0;" :: "n"(N));
}

__device__ __forceinline__ uint32_t packh(float x, float y) {
    __nv_bfloat162 r; r.x = __float2bfloat16(x); r.y = __float2bfloat16(y);
    return *(uint32_t*)&r;
}
__device__ __forceinline__ uint32_t packl(float x, float y, uint32_t hp) {
    __nv_bfloat162 h = *(__nv_bfloat162*)&hp;
    __nv_bfloat162 r;
    r.x = __float2bfloat16(x - __bfloat162float(h.x));
    r.y = __float2bfloat16(y - __bfloat162float(h.y));
    return *(uint32_t*)&r;
}

// Fast exp (FFMA pipe). |rel err| ~3e-6.
__device__ __forceinline__ float fexp(float x) {
    x = fmaxf(fminf(x, 80.f), -87.f);
    float y = x * 1.4426950408889634f;
    int   i = __float2int_rn(y);
    float f = y - (float)i;
    float p = 1.3333558146e-3f;
    p = fmaf(p, f, 9.6181291918e-3f);
    p = fmaf(p, f, 5.5504108664e-2f);
    p = fmaf(p, f, 2.4022650696e-1f);
    p = fmaf(p, f, 6.9314718056e-1f);
    p = fmaf(p, f, 1.0f);
    return __int_as_float(__float_as_int(p) + (i << 23));
}

// ---------------------------------------------------------------------------
// fp32 -> bf16 hi/lo splits
// ---------------------------------------------------------------------------
__global__ __launch_bounds__(256)
void split_bf16(const float* __restrict__ x, __nv_bfloat16* __restrict__ hi,
                __nv_bfloat16* __restrict__ lo, int n4)
{
    int i = blockIdx.x * 256 + threadIdx.x;
    if (i >= n4) return;
    float4 v = ((const float4*)x)[i];
    uint32_t h0 = packh(v.x, v.y), h1 = packh(v.z, v.w);
    ((uint32_t*)hi)[i * 2]     = h0;
    ((uint32_t*)hi)[i * 2 + 1] = h1;
    ((uint32_t*)lo)[i * 2]     = packl(v.x, v.y, h0);
    ((uint32_t*)lo)[i * 2 + 1] = packl(v.z, v.w, h1);
}

__global__ __launch_bounds__(256)
void split_w8(const float* __restrict__ w0, const float* __restrict__ w1,
              const float* __restrict__ w2, const float* __restrict__ w3,
              const float* __restrict__ w4, const float* __restrict__ w5,
              const float* __restrict__ w6, const float* __restrict__ w7,
              __nv_bfloat16* __restrict__ hi, __nv_bfloat16* __restrict__ lo)
{
    const float* ws[8] = {w0, w1, w2, w3, w4, w5, w6, w7};
    const int z = blockIdx.y;
    const float* x = ws[z];
    int i = blockIdx.x * 256 + threadIdx.x;
    float4 v = ((const float4*)x)[i];
    uint32_t h0 = packh(v.x, v.y), h1 = packh(v.z, v.w);
    size_t o = (size_t)z * WSZ / 4 + i;
    ((uint32_t*)hi)[o * 2]     = h0;
    ((uint32_t*)hi)[o * 2 + 1] = h1;
    ((uint32_t*)lo)[o * 2]     = packl(v.x, v.y, h0);
    ((uint32_t*)lo)[o * 2 + 1] = packl(v.z, v.w, h1);
}

// ---------------------------------------------------------------------------
// HMMA GEMM. blockIdx.z selects weight (Bh/Bl offset z*WSZ), bias and output
// (A/B variants) — lets two GEMMs sharing the A panel run in one launch.
// ---------------------------------------------------------------------------
#define SSTR 40
#define GEMM_SMEM (8 * 128 * SSTR * 2)

__global__ __launch_bounds__(256)
void gemm_hmma(const __nv_bfloat16* __restrict__ Ah, const __nv_bfloat16* __restrict__ Al,
               const __nv_bfloat16* __restrict__ Bh0, const __nv_bfloat16* __restrict__ Bl0,
               const float* __restrict__ biasA, const float* __restrict__ biasB,
               float* __restrict__ Y,
               __nv_bfloat16* __restrict__ YhA, __nv_bfloat16* __restrict__ YlA,
               __nv_bfloat16* __restrict__ YhB, __nv_bfloat16* __restrict__ YlB,
               int ep, int obf, int x3)
{
    extern __shared__ __align__(16) __nv_bfloat16 gsm[];

    const int z = blockIdx.z;
    const __nv_bfloat16* Bh = Bh0 + (size_t)z * WSZ;
    const __nv_bfloat16* Bl = Bl0 + (size_t)z * WSZ;
    const float* bias = z ? biasB : biasA;
    __nv_bfloat16* Yh = z ? YhB : YhA;
    __nv_bfloat16* Yl = z ? YlB : YlA;

    const int tid  = threadIdx.x;
    const int wid  = tid >> 5;
    const int lane = tid & 31;
    const int m0   = blockIdx.x * 128;
    const int n0   = blockIdx.y * 128;
    const int wm   = (wid & 1) * 64;
    const int wn   = (wid >> 1) * 32;

#define SA(bd, hl) (gsm + ((bd) * 2 + (hl)) * (128 * SSTR))
#define SB(bd, hl) (gsm + (4 + (bd) * 2 + (hl)) * (128 * SSTR))

    float c[4][4][4];
#pragma unroll
    for (int mi = 0; mi < 4; mi++)
#pragma unroll
        for (int ni = 0; ni < 4; ni++)
#pragma unroll
            for (int e = 0; e < 4; e++) c[mi][ni][e] = 0.f;

    auto issue = [&](int kc, int bd) {
#pragma unroll
        for (int u = 0; u < 2; u++) {
            int idx = u * 256 + tid;
            int row = idx >> 2;
            int f4  = idx & 3;
            int soff = row * SSTR + f4 * 8;
            const size_t ga = (size_t)(m0 + row) * 256 + kc * 32 + f4 * 8;
            const size_t gb = (size_t)(n0 + row) * 256 + kc * 32 + f4 * 8;
            cp16(smem_u32(SA(bd, 0) + soff), Ah + ga);
            cp16(smem_u32(SB(bd, 0) + soff), Bh + gb);
            if (x3) {
                cp16(smem_u32(SA(bd, 1) + soff), Al + ga);
                cp16(smem_u32(SB(bd, 1) + soff), Bl + gb);
            }
        }
        CP_COMMIT();
    };

    issue(0, 0);
    for (int kc = 0; kc < 8; kc++) {
        const int cur = kc & 1;
        if (kc < 7) { issue(kc + 1, cur ^ 1); cp_wait<1>(); }
        else        { cp_wait<0>(); }
        __syncthreads();

#pragma unroll
        for (int ks = 0; ks < 2; ks++) {
            const int kb = ks * 16;
            uint32_t ah[4][4], al[4][4];
            {
                const int r  = wm + (lane & 15);
                const int kk = kb + (lane >> 4) * 8;
#pragma unroll
                for (int mi = 0; mi < 4; mi++) {
                    LDSM_X4(ah[mi], smem_u32(SA(cur, 0) + (r + mi * 16) * SSTR + kk));
                    if (x3) LDSM_X4(al[mi], smem_u32(SA(cur, 1) + (r + mi * 16) * SSTR + kk));
                }
            }
            uint32_t bh[2][4], bl[2][4];
            {
                const int nr = (lane & 7) + ((lane >> 4) & 1) * 8;
                const int kk = kb + ((lane >> 3) & 1) * 8;
#pragma unroll
                for (int ng = 0; ng < 2; ng++) {
                    LDSM_X4(bh[ng], smem_u32(SB(cur, 0) + (wn + ng * 16 + nr) * SSTR + kk));
                    if (x3) LDSM_X4(bl[ng], smem_u32(SB(cur, 1) + (wn + ng * 16 + nr) * SSTR + kk));
                }
            }
#pragma unroll
            for (int mi = 0; mi < 4; mi++)
#pragma unroll
                for (int ni = 0; ni < 4; ni++) {
                    uint32_t* bH = &bh[ni >> 1][(ni & 1) * 2];
                    MMA_BF16(c[mi][ni], ah[mi], bH);
                    if (x3) {
                        uint32_t* bL = &bl[ni >> 1][(ni & 1) * 2];
                        MMA_BF16(c[mi][ni], ah[mi], bL);
                        MMA_BF16(c[mi][ni], al[mi], bH);
                    }
                }
        }
        __syncthreads();
    }

    const int mrow = m0 + wm + (lane >> 2);
    const int ncol = n0 + wn + 2 * (lane & 3);
#pragma unroll
    for (int mi = 0; mi < 4; mi++) {
#pragma unroll
        for (int ni = 0; ni < 4; ni++) {
            const int col = ncol + ni * 8;
            float v[4];
#pragma unroll
            for (int e = 0; e < 4; e++) {
                float t = c[mi][ni][e] + bias[col + (e & 1)];
                if (ep >= 1) t = (t > 0.f) ? (t + 1.f) : __expf(t);
                if (ep == 2) t = sqrtf(fmaxf(t, 1e-24f));
                v[e] = t;
            }
            const size_t i0 = (size_t)(mrow + mi * 16) * 256 + col;
            const size_t i1 = (size_t)(mrow + mi * 16 + 8) * 256 + col;
            if (obf) {
                uint32_t h0 = packh(v[0], v[1]), h1 = packh(v[2], v[3]);
                *(uint32_t*)&Yh[i0] = h0;
                *(uint32_t*)&Yh[i1] = h1;
                if (obf == 1) {
                    *(uint32_t*)&Yl[i0] = packl(v[0], v[1], h0);
                    *(uint32_t*)&Yl[i1] = packl(v[2], v[3], h1);
                }
            } else {
                *(float2*)(Y + i0) = make_float2(v[0], v[1]);
                *(float2*)(Y + i1) = make_float2(v[2], v[3]);
            }
        }
    }
#undef SA
#undef SB
}

// ---------------------------------------------------------------------------
// Row scalars from bf16 hi/lo
// ---------------------------------------------------------------------------
__global__ __launch_bounds__(256)
void rowsum_kernel(const __nv_bfloat16* __restrict__ Mh, const __nv_bfloat16* __restrict__ Ml,
                   const __nv_bfloat16* __restrict__ Sh, const __nv_bfloat16* __restrict__ Sl,
                   float* __restrict__ A)
{
    const int w    = (blockIdx.x * blockDim.x + threadIdx.x) >> 5;
    const int lane = threadIdx.x & 31;
    const int s  = w & 511;
    const int bh = w >> 9;
    const int b  = bh >> 2, h = bh & 3;
    const size_t base = ((size_t)(b * 512 + s) * 256) + h * 64 + lane * 2;
    float2 mh = __bfloat1622float2(*(const __nv_bfloat162*)&Mh[base]);
    float2 ml = __bfloat1622float2(*(const __nv_bfloat162*)&Ml[base]);
    float2 sh = __bfloat1622float2(*(const __nv_bfloat162*)&Sh[base]);
    float2 sl = __bfloat1622float2(*(const __nv_bfloat162*)&Sl[base]);
    float m0 = mh.x + ml.x, m1 = mh.y + ml.y;
    float s0 = sh.x + sl.x, s1 = sh.y + sl.y;
    float sum = m0 * m0 + m1 * m1 + s0 * s0 + s1 * s1;
#pragma unroll
    for (int o = 16; o; o >>= 1) sum += __shfl_xor_sync(~0u, sum, o);
    if (!lane) A[w] = sum;
}

// ---------------------------------------------------------------------------
// Tensor-core attention v5 (256 threads, R10 layout) with DEFERRED phase-A
// epilogue: exp/mask/store for kt-1 runs before the MMA loop of kt, so the
// FMA-pipe exp work overlaps tensor-pipe MMAs instead of serializing.
// ---------------------------------------------------------------------------
#define SC_STR 516
#define QS 136
#define VS 72
#define BFREG_BYTES 69632
#define ATT_SMEM_BYTES ((640 + 64*SC_STR) * 4 + BFREG_BYTES)   // 204288

__global__ __launch_bounds__(256)
void attn_tc(const float* __restrict__ mask, float* __restrict__ probs)
{
    extern __shared__ __align__(16) float sm[];
    float* aqs   = sm;
    float* aks   = sm + 64;
    float* invzs = sm + 576;
    float* Ssc   = sm + 640;
    __nv_bfloat16* bfr = (__nv_bfloat16*)(sm + 640 + 64 * SC_STR);
    __nv_bfloat16* Khi0 = bfr;
    __nv_bfloat16* Klo0 = bfr + 64 * QS;
    __nv_bfloat16* Khi1 = bfr + 2 * 64 * QS;
    __nv_bfloat16* Klo1 = bfr + 3 * 64 * QS;
    __nv_bfloat16* Phi  = bfr;
    __nv_bfloat16* P2hi = bfr + 64 * VS;
    __nv_bfloat16* Vmh0 = bfr + 2 * 64 * VS;
    __nv_bfloat16* Vch0 = bfr + 3 * 64 * VS;
    __nv_bfloat16* Vmh1 = bfr + 4 * 64 * VS;
    __nv_bfloat16* Vch1 = bfr + 5 * 64 * VS;

    const int tid  = threadIdx.x;
    const int wid  = tid >> 5;
    const int lane = tid & 31;
    const int g    = lane >> 2;
    const int t    = lane & 3;
    const int q0   = blockIdx.x * 64;
    const int h    = blockIdx.y;
    const int b    = blockIdx.z;
    const int wm2  = (wid & 1) * 32;
    const int wn   = (wid >> 1) * 16;

    const float* mrow = mask + ((size_t)b * 512 + q0) * 512;

    auto issueK = [&](int kt, __nv_bfloat16* KH, __nv_bfloat16* KL) {
#pragma unroll
        for (int u = 0; u < 4; u++) {
            int idx = u * 256 + tid;
            int row = idx >> 4;
            int c8  = (idx & 15) * 8;
            const size_t src = ((size_t)(b * 512 + kt * 64 + row) * 256) + h * 64
                             + (c8 < 64 ? c8 : c8 - 64);
            const __nv_bfloat16* ph = (c8 < 64) ? g_mkh : g_skh;
            const __nv_bfloat16* pl = (c8 < 64) ? g_mkl : g_skl;
            cp16(smem_u32(&KH[row * QS + c8]), ph + src);
            cp16(smem_u32(&KL[row * QS + c8]), pl + src);
        }
        CP_COMMIT();
    };
    auto issueV = [&](int kt, __nv_bfloat16* VM, __nv_bfloat16* VC) {
#pragma unroll
        for (int u = 0; u < 2; u++) {
            int idx = u * 256 + tid;
            int row = idx >> 3;
            int d8  = (idx & 7) * 8;
            const size_t src = ((size_t)(b * 512 + kt * 64 + row) * 256) + h * 64 + d8;
            cp16(smem_u32(&VM[row * VS + d8]), g_mvh + src);
            cp16(smem_u32(&VC[row * VS + d8]), g_cvh + src);
        }
        CP_COMMIT();
    };

    if (tid < 64) aqs[tid] = g_aq[(b * 4 + h) * 512 + q0 + tid];
    aks[tid]       = g_ak[(b * 4 + h) * 512 + tid];
    aks[tid + 256] = g_ak[(b * 4 + h) * 512 + 256 + tid];

    issueK(0, Khi0, Klo0);

    // ---- stage Q in buf1 ----
#pragma unroll
    for (int u = 0; u < 4; u++) {
        int idx = u * 256 + tid;
        int row = idx >> 4;
        int c8  = (idx & 15) * 8;
        const size_t src = ((size_t)(b * 512 + q0 + row) * 256) + h * 64
                         + (c8 < 64 ? c8 : c8 - 64);
        const __nv_bfloat16* ph = (c8 < 64) ? g_mqh : g_sqh;
        const __nv_bfloat16* pl = (c8 < 64) ? g_mql : g_sql;
        *(uint4*)&Khi1[row * QS + c8] = *(const uint4*)(ph + src);
        *(uint4*)&Klo1[row * QS + c8] = *(const uint4*)(pl + src);
    }
    __syncthreads();

    // ---- hoist Q fragments ----
    uint32_t qfh[8][2][4], qfl[8][2][4];
    {
        const int ar = wm2 + (lane & 15);
#pragma unroll
        for (int ks = 0; ks < 8; ks++) {
            const int akk = ks * 16 + (lane >> 4) * 8;
#pragma unroll
            for (int mi = 0; mi < 2; mi++) {
                LDSM_X4(qfh[ks][mi], smem_u32(&Khi1[(ar + mi * 16) * QS + akk]));
                LDSM_X4(qfl[ks][mi], smem_u32(&Klo1[(ar + mi * 16) * QS + akk]));
            }
        }
    }

    // deferred-epilogue state: summed dot for kt-1
    float svp[2][2][4];

    auto epilogueA = [&](int ktp) {
#pragma unroll
        for (int mi = 0; mi < 2; mi++) {
            const int i0 = wm2 + mi * 16 + g;
#pragma unroll
            for (int ni = 0; ni < 2; ni++) {
                const int j = ktp * 64 + wn + ni * 8 + 2 * t;
                const float akj0 = aks[j], akj1 = aks[j + 1];
                float2 m0 = *(const float2*)&mrow[(size_t)i0 * 512 + j];
                float2 m1 = *(const float2*)&mrow[(size_t)(i0 + 8) * 512 + j];
                float d00 = aqs[i0]     + akj0 - 2.f * svp[mi][ni][0];
                float d01 = aqs[i0]     + akj1 - 2.f * svp[mi][ni][1];
                float d10 = aqs[i0 + 8] + akj0 - 2.f * svp[mi][ni][2];
                float d11 = aqs[i0 + 8] + akj1 - 2.f * svp[mi][ni][3];
                *(float2*)&Ssc[i0 * SC_STR + j] =
                    make_float2(fexp(-d00) * 0.125f + m0.x, fexp(-d01) * 0.125f + m0.y);
                *(float2*)&Ssc[(i0 + 8) * SC_STR + j] =
                    make_float2(fexp(-d10) * 0.125f + m1.x, fexp(-d11) * 0.125f + m1.y);
            }
        }
    };

    // ================= Phase A =================
    for (int kt = 0; kt < 8; kt++) {
        cp_wait<0>();
        __syncthreads();
        __nv_bfloat16* KH = (kt & 1) ? Khi1 : Khi0;
        __nv_bfloat16* KL = (kt & 1) ? Klo1 : Klo0;
        if (kt < 7) issueK(kt + 1, (kt & 1) ? Khi0 : Khi1, (kt & 1) ? Klo0 : Klo1);

        // deferred epilogue for previous tile (overlaps with upcoming MMAs
        // of other warps and this warp's cp.async)
        if (kt > 0) epilogueA(kt - 1);

        float acc[2][2][4], acl[2][2][4], acm[2][2][4];
#pragma unroll
        for (int mi = 0; mi < 2; mi++)
#pragma unroll
            for (int ni = 0; ni < 2; ni++)
#pragma unroll
                for (int e = 0; e < 4; e++) {
                    acc[mi][ni][e] = 0.f; acl[mi][ni][e] = 0.f; acm[mi][ni][e] = 0.f;
                }

#pragma unroll
        for (int ks = 0; ks < 8; ks++) {
            uint32_t bh[4], bl[4];
            const int nr  = (lane & 7) + ((lane >> 4) & 1) * 8;
            const int kk2 = ks * 16 + ((lane >> 3) & 1) * 8;
            LDSM_X4(bh, smem_u32(&KH[(wn + nr) * QS + kk2]));
            LDSM_X4(bl, smem_u32(&KL[(wn + nr) * QS + kk2]));
#pragma unroll
            for (int mi = 0; mi < 2; mi++)
#pragma unroll
                for (int ni = 0; ni < 2; ni++) {
                    MMA_BF16(acc[mi][ni], qfh[ks][mi], (&bh[ni * 2]));
                    MMA_BF16(acl[mi][ni], qfh[ks][mi], (&bl[ni * 2]));
                    MMA_BF16(acm[mi][ni], qfl[ks][mi], (&bh[ni * 2]));
                }
        }

        // fold accumulators into svp (consumed next iteration)
#pragma unroll
        for (int mi = 0; mi < 2; mi++)
#pragma unroll
            for (int ni = 0; ni < 2; ni++)
#pragma unroll
                for (int e = 0; e < 4; e++)
                    svp[mi][ni][e] = acc[mi][ni][e] + acl[mi][ni][e] + acm[mi][ni][e];
    }
    epilogueA(7);
    __syncthreads();

    // ================= Phase B: softmax =================
    {
        const int row = tid >> 2, sub = tid & 3;
        float m = -3.0e38f;
        for (int k = sub; k < 512; k += 4) m = fmaxf(m, Ssc[row * SC_STR + k]);
        m = fmaxf(m, __shfl_xor_sync(~0u, m, 1));
        m = fmaxf(m, __shfl_xor_sync(~0u, m, 2));
        float s = 0.f;
        for (int k = sub; k < 512; k += 4) {
            float e = fexp(Ssc[row * SC_STR + k] - m);
            Ssc[row * SC_STR + k] = e;
            s += e;
        }
        s += __shfl_xor_sync(~0u, s, 1);
        s += __shfl_xor_sync(~0u, s, 2);
        if (sub == 0) invzs[row] = 1.f / s;
    }
    __syncthreads();

    issueV(0, Vmh0, Vch0);

    {
        const size_t pbase = (((size_t)(b * 4 + h)) * 512 + q0) * 512;
#pragma unroll
        for (int u = 0; u < 32; u++) {
            int lin = u * 256 + tid;
            int i   = lin >> 7;
            int k4  = (lin & 127) << 2;
            float z = invzs[i];
            float4 p = *(float4*)&Ssc[i * SC_STR + k4];
            p.x *= z; p.y *= z; p.z *= z; p.w *= z;
            *(float4*)&Ssc[i * SC_STR + k4] = p;
            *(float4*)(probs + pbase + (size_t)i * 512 + k4) = p;
        }
    }

    // ================= Phase C: PV (bf16x1, V double-buffered) =================
    float am[2][2][4], ac2[2][2][4];
#pragma unroll
    for (int mi = 0; mi < 2; mi++)
#pragma unroll
        for (int ni = 0; ni < 2; ni++)
#pragma unroll
            for (int e = 0; e < 4; e++) { am[mi][ni][e] = 0.f; ac2[mi][ni][e] = 0.f; }

    for (int kt = 0; kt < 8; kt++) {
        __syncthreads();
#pragma unroll
        for (int u = 0; u < 8; u++) {
            int idx = u * 256 + tid;
            int row = idx >> 5;
            int cp  = (idx & 31) * 2;
            float2 p = *(const float2*)&Ssc[row * SC_STR + kt * 64 + cp];
            *(uint32_t*)&Phi[row * VS + cp]  = packh(p.x, p.y);
            *(uint32_t*)&P2hi[row * VS + cp] = packh(p.x * p.x, p.y * p.y);
        }
        cp_wait<0>();
        __syncthreads();
        __nv_bfloat16* VM = (kt & 1) ? Vmh1 : Vmh0;
        __nv_bfloat16* VC = (kt & 1) ? Vch1 : Vch0;
        if (kt < 7) issueV(kt + 1, (kt & 1) ? Vmh0 : Vmh1, (kt & 1) ? Vch0 : Vch1);

#pragma unroll
        for (int ks = 0; ks < 4; ks++) {
            const int s0 = ks * 16;
            uint32_t ph[2][4], qh[2][4];
            const int ar = wm2 + (lane & 15);
            const int ac = s0 + (lane >> 4) * 8;
#pragma unroll
            for (int mi = 0; mi < 2; mi++) {
                LDSM_X4(ph[mi], smem_u32(&Phi [(ar + mi * 16) * VS + ac]));
                LDSM_X4(qh[mi], smem_u32(&P2hi[(ar + mi * 16) * VS + ac]));
            }
            uint32_t bmh[4], bch[4];
            const int sr = (lane & 7) + ((lane >> 3) & 1) * 8;
            const int d8 = (lane >> 4) * 8;
            const int vbase = (s0 + sr) * VS + wn + d8;
            LDSM_X4_T(bmh, smem_u32(&VM[vbase]));
            LDSM_X4_T(bch, smem_u32(&VC[vbase]));
#pragma unroll
            for (int mi = 0; mi < 2; mi++)
#pragma unroll
                for (int ni = 0; ni < 2; ni++) {
                    MMA_BF16(am[mi][ni],  ph[mi], (&bmh[ni * 2]));
                    MMA_BF16(ac2[mi][ni], qh[mi], (&bch[ni * 2]));
                }
        }
    }

    // ---- store ctx (hi only) ----
#pragma unroll
    for (int mi = 0; mi < 2; mi++) {
#pragma unroll
        for (int ni = 0; ni < 2; ni++) {
            const int row = q0 + wm2 + mi * 16 + g;
            const int col = h * 64 + wn + ni * 8 + 2 * t;
            const size_t i0 = ((size_t)(b * 512 + row)) * 256 + col;
            const size_t i1 = ((size_t)(b * 512 + row + 8)) * 256 + col;
            *(uint32_t*)&g_cmh[i0] = packh(am[mi][ni][0], am[mi][ni][1]);
            *(uint32_t*)&g_cmh[i1] = packh(am[mi][ni][2], am[mi][ni][3]);
            *(uint32_t*)&g_cch[i0] = packh(ac2[mi][ni][0], ac2[mi][ni][1]);
            *(uint32_t*)&g_cch[i1] = packh(ac2[mi][ni][2], ac2[mi][ni][3]);
        }
    }
}

// ---------------------------------------------------------------------------
// LayerNorm: warp-per-row (8 rows per block)
// ---------------------------------------------------------------------------
__global__ __launch_bounds__(256)
void ln_kernel(const float* __restrict__ D, const float* __restrict__ X,
               const float* __restrict__ lw, const float* __restrict__ lb,
               float* __restrict__ O)
{
    const int warp = threadIdx.x >> 5, lane = threadIdx.x & 31;
    const int r = blockIdx.x * 8 + warp;
    const size_t base = (size_t)r * 256 + lane * 8;
    float4 d0 = *(const float4*)(D + base);
    float4 d1 = *(const float4*)(D + base + 4);
    float4 x0 = *(const float4*)(X + base);
    float4 x1 = *(const float4*)(X + base + 4);
    float v[8] = {d0.x + x0.x, d0.y + x0.y, d0.z + x0.z, d0.w + x0.w,
                  d1.x + x1.x, d1.y + x1.y, d1.z + x1.z, d1.w + x1.w};
    float s1 = 0.f, s2 = 0.f;
#pragma unroll
    for (int e = 0; e < 8; e++) { s1 += v[e]; s2 += v[e] * v[e]; }
#pragma unroll
    for (int o = 16; o; o >>= 1) {
        s1 += __shfl_xor_sync(~0u, s1, o);
        s2 += __shfl_xor_sync(~0u, s2, o);
    }
    float u   = s1 * (1.f / 256.f);
    float var = fmaxf(s2 * (1.f / 256.f) - u * u, 0.f);
    float is  = rsqrtf(var + 1e-12f);
    float y[8];
#pragma unroll
    for (int e = 0; e < 8; e++)
        y[e] = fmaf(lw[lane * 8 + e], (v[e] - u) * is, lb[lane * 8 + e]);
    *(float4*)(O + base)     = make_float4(y[0], y[1], y[2], y[3]);
    *(float4*)(O + base + 4) = make_float4(y[4], y[5], y[6], y[7]);
}

// ---------------------------------------------------------------------------
// kernel_launch
// ---------------------------------------------------------------------------
extern "C" void kernel_launch(void* const* d_in, const int* in_sizes, int n_in,
                              void* d_out, int out_size)
{
    (void)in_sizes; (void)n_in; (void)out_size;
    const float* in_mean = (const float*)d_in[0];
    const float* in_cov  = (const float*)d_in[1];
    const float* mask    = (const float*)d_in[2];
    const float* W[8]    = { (const float*)d_in[3],  (const float*)d_in[5],
                             (const float*)d_in[7],  (const float*)d_in[9],
                             (const float*)d_in[11], (const float*)d_in[13],
                             (const float*)d_in[15], (const float*)d_in[17] };
    const float* bia[8]  = { (const float*)d_in[4],  (const float*)d_in[6],
                             (const float*)d_in[8],  (const float*)d_in[10],
                             (const float*)d_in[12], (const float*)d_in[14],
                             (const float*)d_in[16], (const float*)d_in[18] };
    const float* lw  = (const float*)d_in[19];
    const float* lb  = (const float*)d_in[20];
    float* out = (float*)d_out;

    float *dm, *dc, *aq, *ak;
    cudaGetSymbolAddress((void**)&dm, g_dm);
    cudaGetSymbolAddress((void**)&dc, g_dc);
    cudaGetSymbolAddress((void**)&aq, g_aq);
    cudaGetSymbolAddress((void**)&ak, g_ak);

    __nv_bfloat16 *xmh, *xml, *xch, *xcl, *cmh, *cml, *cch, *ccl, *wh, *wl;
    __nv_bfloat16 *mqh, *mql, *mkh, *mkl, *mvh, *mvl, *sqh, *sql, *skh, *skl, *cvh, *cvl;
    cudaGetSymbolAddress((void**)&xmh, g_xmh);  cudaGetSymbolAddress((void**)&xml, g_xml);
    cudaGetSymbolAddress((void**)&xch, g_xch);  cudaGetSymbolAddress((void**)&xcl, g_xcl);
    cudaGetSymbolAddress((void**)&cmh, g_cmh);  cudaGetSymbolAddress((void**)&cml, g_cml);
    cudaGetSymbolAddress((void**)&cch, g_cch);  cudaGetSymbolAddress((void**)&ccl, g_ccl);
    cudaGetSymbolAddress((void**)&wh,  g_wh);   cudaGetSymbolAddress((void**)&wl,  g_wl);
    cudaGetSymbolAddress((void**)&mqh, g_mqh);  cudaGetSymbolAddress((void**)&mql, g_mql);
    cudaGetSymbolAddress((void**)&mkh, g_mkh);  cudaGetSymbolAddress((void**)&mkl, g_mkl);
    cudaGetSymbolAddress((void**)&mvh, g_mvh);  cudaGetSymbolAddress((void**)&mvl, g_mvl);
    cudaGetSymbolAddress((void**)&sqh, g_sqh);  cudaGetSymbolAddress((void**)&sql, g_sql);
    cudaGetSymbolAddress((void**)&skh, g_skh);  cudaGetSymbolAddress((void**)&skl, g_skl);
    cudaGetSymbolAddress((void**)&cvh, g_cvh);  cudaGetSymbolAddress((void**)&cvl, g_cvl);

    cudaFuncSetAttribute(attn_tc, cudaFuncAttributeMaxDynamicSharedMemorySize,
                         ATT_SMEM_BYTES);
    cudaFuncSetAttribute(gemm_hmma, cudaFuncAttributeMaxDynamicSharedMemorySize,
                         GEMM_SMEM);

    // ---- input/weight splits ----
    split_bf16<<<MAT / 4 / 256, 256>>>(in_mean, xmh, xml, MAT / 4);
    split_bf16<<<MAT / 4 / 256, 256>>>(in_cov,  xch, xcl, MAT / 4);
    split_w8<<<dim3(WSZ / 4 / 256, 8), 256>>>(W[0], W[1], W[2], W[3],
                                              W[4], W[5], W[6], W[7], wh, wl);

    dim3 gg1(MROWS / 128, 2, 1);
    dim3 gg2(MROWS / 128, 2, 2);

    // ---- projections: paired launches (share A panel) ----
    gemm_hmma<<<gg2, 256, GEMM_SMEM>>>(xmh, xml, wh + 0*WSZ, wl + 0*WSZ,
                                       bia[0], bia[1], nullptr,
                                       mqh, mql, mkh, mkl, 0, 1, 1);
    gemm_hmma<<<gg2, 256, GEMM_SMEM>>>(xch, xcl, wh + 3*WSZ, wl + 3*WSZ,
                                       bia[3], bia[4], nullptr,
                                       sqh, sql, skh, skl, 2, 1, 1);
    gemm_hmma<<<gg1, 256, GEMM_SMEM>>>(xmh, xml, wh + 2*WSZ, wl + 2*WSZ,
                                       bia[2], bia[2], nullptr,
                                       mvh, mvl, nullptr, nullptr, 0, 2, 0);
    gemm_hmma<<<gg1, 256, GEMM_SMEM>>>(xch, xcl, wh + 5*WSZ, wl + 5*WSZ,
                                       bia[5], bia[5], nullptr,
                                       cvh, cvl, nullptr, nullptr, 1, 2, 0);

    // ---- row scalars ----
    rowsum_kernel<<<NROW / 8, 256>>>(mqh, mql, sqh, sql, aq);
    rowsum_kernel<<<NROW / 8, 256>>>(mkh, mkl, skh, skl, ak);

    // ---- tensor-core attention ----
    attn_tc<<<dim3(SS / 64, NH, BB), 256, ATT_SMEM_BYTES>>>(mask, out + 2 * (size_t)MAT);

    // ---- output denses (x1, fp32 out) ----
    gemm_hmma<<<gg1, 256, GEMM_SMEM>>>(cmh, cml, wh + 6*WSZ, wl + 6*WSZ,
                                       bia[6], bia[6], dm,
                                       nullptr, nullptr, nullptr, nullptr, 0, 0, 0);
    gemm_hmma<<<gg1, 256, GEMM_SMEM>>>(cch, ccl, wh + 7*WSZ, wl + 7*WSZ,
                                       bia[7], bia[7], dc,
                                       nullptr, nullptr, nullptr, nullptr, 0, 0, 0);

    // ---- residual + layernorm ----
    ln_kernel<<<MROWS / 8, 256>>>(dm, in_mean, lw, lb, out);
    ln_kernel<<<MROWS / 8, 256>>>(dc, in_cov,  lw, lb, out + (size_t)MAT);
}

// round 14
// speedup vs baseline: 1.0594x; 1.0594x over previous
#include <cuda_runtime.h>
#include <cuda_bf16.h>
#include <stdint.h>
#include <math.h>

// ---------------------------------------------------------------------------
// Problem constants
// ---------------------------------------------------------------------------
#define BB   64
#define SS   512
#define HID  256
#define NH   4
#define DH   64
#define MROWS (BB*SS)            // 32768
#define MAT   (MROWS*HID)        // 8388608
#define NROW  (BB*NH*SS)         // 131072
#define WSZ   (HID*HID)          // 65536

// ---------------------------------------------------------------------------
// Scratch (device globals; no allocation allowed)
// ---------------------------------------------------------------------------
__device__ float g_dm[MAT];
__device__ float g_dc[MAT];
__device__ float g_aq[NROW];
__device__ float g_ak[NROW];
__device__ __nv_bfloat16 g_xmh[MAT], g_xml[MAT];
__device__ __nv_bfloat16 g_xch[MAT], g_xcl[MAT];
__device__ __nv_bfloat16 g_cmh[MAT], g_cml[MAT];
__device__ __nv_bfloat16 g_cch[MAT], g_ccl[MAT];
__device__ __nv_bfloat16 g_wh[8*WSZ], g_wl[8*WSZ];
__device__ __nv_bfloat16 g_mqh[MAT], g_mql[MAT];
__device__ __nv_bfloat16 g_mkh[MAT], g_mkl[MAT];
__device__ __nv_bfloat16 g_mvh[MAT], g_mvl[MAT];
__device__ __nv_bfloat16 g_sqh[MAT], g_sql[MAT];
__device__ __nv_bfloat16 g_skh[MAT], g_skl[MAT];
__device__ __nv_bfloat16 g_cvh[MAT], g_cvl[MAT];

// ---------------------------------------------------------------------------
// Helpers
// ---------------------------------------------------------------------------
__device__ __forceinline__ uint32_t smem_u32(const void* p) {
    uint32_t a;
    asm("{ .reg .u64 t; cvta.to.shared.u64 t, %1; cvt.u32.u64 %0, t; }"
        : "=r"(a) : "l"(p));
    return a;
}

#define LDSM_X4(d, addr) \
    asm volatile("ldmatrix.sync.aligned.m8n8.x4.shared.b16 {%0,%1,%2,%3}, [%4];" \
        : "=r"((d)[0]), "=r"((d)[1]), "=r"((d)[2]), "=r"((d)[3]) : "r"(addr))

#define LDSM_X4_T(d, addr) \
    asm volatile("ldmatrix.sync.aligned.m8n8.x4.trans.shared.b16 {%0,%1,%2,%3}, [%4];" \
        : "=r"((d)[0]), "=r"((d)[1]), "=r"((d)[2]), "=r"((d)[3]) : "r"(addr))

#define MMA_BF16(c, a, b) \
    asm volatile("mma.sync.aligned.m16n8k16.row.col.f32.bf16.bf16.f32 " \
        "{%0,%1,%2,%3}, {%4,%5,%6,%7}, {%8,%9}, {%0,%1,%2,%3};" \
        : "+f"((c)[0]), "+f"((c)[1]), "+f"((c)[2]), "+f"((c)[3]) \
        : "r"((a)[0]), "r"((a)[1]), "r"((a)[2]), "r"((a)[3]), \
          "r"((b)[0]), "r"((b)[1]))

__device__ __forceinline__ void cp16(uint32_t saddr, const void* g) {
    asm volatile("cp.async.cg.shared.global [%0], [%1], 16;" :: "r"(saddr), "l"(g));
}
#define CP_COMMIT() asm volatile("cp.async.commit_group;")
template<int N> __device__ __forceinline__ void cp_wait() {
    asm volatile("cp.async.wait_group %0;" :: "n"(N));
}

__device__ __forceinline__ uint32_t packh(float x, float y) {
    __nv_bfloat162 r; r.x = __float2bfloat16(x); r.y = __float2bfloat16(y);
    return *(uint32_t*)&r;
}
__device__ __forceinline__ uint32_t packl(float x, float y, uint32_t hp) {
    __nv_bfloat162 h = *(__nv_bfloat162*)&hp;
    __nv_bfloat162 r;
    r.x = __float2bfloat16(x - __bfloat162float(h.x));
    r.y = __float2bfloat16(y - __bfloat162float(h.y));
    return *(uint32_t*)&r;
}

// Fast exp (FFMA pipe). |rel err| ~3e-6.
__device__ __forceinline__ float fexp(float x) {
    x = fmaxf(fminf(x, 80.f), -87.f);
    float y = x * 1.4426950408889634f;
    int   i = __float2int_rn(y);
    float f = y - (float)i;
    float p = 1.3333558146e-3f;
    p = fmaf(p, f, 9.6181291918e-3f);
    p = fmaf(p, f, 5.5504108664e-2f);
    p = fmaf(p, f, 2.4022650696e-1f);
    p = fmaf(p, f, 6.9314718056e-1f);
    p = fmaf(p, f, 1.0f);
    return __int_as_float(__float_as_int(p) + (i << 23));
}

// ---------------------------------------------------------------------------
// fp32 -> bf16 hi/lo splits
// ---------------------------------------------------------------------------
__global__ __launch_bounds__(256)
void split_bf16(const float* __restrict__ x, __nv_bfloat16* __restrict__ hi,
                __nv_bfloat16* __restrict__ lo, int n4)
{
    int i = blockIdx.x * 256 + threadIdx.x;
    if (i >= n4) return;
    float4 v = ((const float4*)x)[i];
    uint32_t h0 = packh(v.x, v.y), h1 = packh(v.z, v.w);
    ((uint32_t*)hi)[i * 2]     = h0;
    ((uint32_t*)hi)[i * 2 + 1] = h1;
    ((uint32_t*)lo)[i * 2]     = packl(v.x, v.y, h0);
    ((uint32_t*)lo)[i * 2 + 1] = packl(v.z, v.w, h1);
}

__global__ __launch_bounds__(256)
void split_w8(const float* __restrict__ w0, const float* __restrict__ w1,
              const float* __restrict__ w2, const float* __restrict__ w3,
              const float* __restrict__ w4, const float* __restrict__ w5,
              const float* __restrict__ w6, const float* __restrict__ w7,
              __nv_bfloat16* __restrict__ hi, __nv_bfloat16* __restrict__ lo)
{
    const float* ws[8] = {w0, w1, w2, w3, w4, w5, w6, w7};
    const int z = blockIdx.y;
    const float* x = ws[z];
    int i = blockIdx.x * 256 + threadIdx.x;
    float4 v = ((const float4*)x)[i];
    uint32_t h0 = packh(v.x, v.y), h1 = packh(v.z, v.w);
    size_t o = (size_t)z * WSZ / 4 + i;
    ((uint32_t*)hi)[o * 2]     = h0;
    ((uint32_t*)hi)[o * 2 + 1] = h1;
    ((uint32_t*)lo)[o * 2]     = packl(v.x, v.y, h0);
    ((uint32_t*)lo)[o * 2 + 1] = packl(v.z, v.w, h1);
}

// ---------------------------------------------------------------------------
// HMMA GEMM, paired via blockIdx.z (z selects weight/bias/output).
// ---------------------------------------------------------------------------
#define SSTR 40
#define GEMM_SMEM (8 * 128 * SSTR * 2)

__global__ __launch_bounds__(256)
void gemm_hmma(const __nv_bfloat16* __restrict__ Ah, const __nv_bfloat16* __restrict__ Al,
               const __nv_bfloat16* __restrict__ Bh0, const __nv_bfloat16* __restrict__ Bl0,
               const float* __restrict__ biasA, const float* __restrict__ biasB,
               float* __restrict__ Y,
               __nv_bfloat16* __restrict__ YhA, __nv_bfloat16* __restrict__ YlA,
               __nv_bfloat16* __restrict__ YhB, __nv_bfloat16* __restrict__ YlB,
               int ep, int obf, int x3)
{
    extern __shared__ __align__(16) __nv_bfloat16 gsm[];

    const int z = blockIdx.z;
    const __nv_bfloat16* Bh = Bh0 + (size_t)z * WSZ;
    const __nv_bfloat16* Bl = Bl0 + (size_t)z * WSZ;
    const float* bias = z ? biasB : biasA;
    __nv_bfloat16* Yh = z ? YhB : YhA;
    __nv_bfloat16* Yl = z ? YlB : YlA;

    const int tid  = threadIdx.x;
    const int wid  = tid >> 5;
    const int lane = tid & 31;
    const int m0   = blockIdx.x * 128;
    const int n0   = blockIdx.y * 128;
    const int wm   = (wid & 1) * 64;
    const int wn   = (wid >> 1) * 32;

#define SA(bd, hl) (gsm + ((bd) * 2 + (hl)) * (128 * SSTR))
#define SB(bd, hl) (gsm + (4 + (bd) * 2 + (hl)) * (128 * SSTR))

    float c[4][4][4];
#pragma unroll
    for (int mi = 0; mi < 4; mi++)
#pragma unroll
        for (int ni = 0; ni < 4; ni++)
#pragma unroll
            for (int e = 0; e < 4; e++) c[mi][ni][e] = 0.f;

    auto issue = [&](int kc, int bd) {
#pragma unroll
        for (int u = 0; u < 2; u++) {
            int idx = u * 256 + tid;
            int row = idx >> 2;
            int f4  = idx & 3;
            int soff = row * SSTR + f4 * 8;
            const size_t ga = (size_t)(m0 + row) * 256 + kc * 32 + f4 * 8;
            const size_t gb = (size_t)(n0 + row) * 256 + kc * 32 + f4 * 8;
            cp16(smem_u32(SA(bd, 0) + soff), Ah + ga);
            cp16(smem_u32(SB(bd, 0) + soff), Bh + gb);
            if (x3) {
                cp16(smem_u32(SA(bd, 1) + soff), Al + ga);
                cp16(smem_u32(SB(bd, 1) + soff), Bl + gb);
            }
        }
        CP_COMMIT();
    };

    issue(0, 0);
    for (int kc = 0; kc < 8; kc++) {
        const int cur = kc & 1;
        if (kc < 7) { issue(kc + 1, cur ^ 1); cp_wait<1>(); }
        else        { cp_wait<0>(); }
        __syncthreads();

#pragma unroll
        for (int ks = 0; ks < 2; ks++) {
            const int kb = ks * 16;
            uint32_t ah[4][4], al[4][4];
            {
                const int r  = wm + (lane & 15);
                const int kk = kb + (lane >> 4) * 8;
#pragma unroll
                for (int mi = 0; mi < 4; mi++) {
                    LDSM_X4(ah[mi], smem_u32(SA(cur, 0) + (r + mi * 16) * SSTR + kk));
                    if (x3) LDSM_X4(al[mi], smem_u32(SA(cur, 1) + (r + mi * 16) * SSTR + kk));
                }
            }
            uint32_t bh[2][4], bl[2][4];
            {
                const int nr = (lane & 7) + ((lane >> 4) & 1) * 8;
                const int kk = kb + ((lane >> 3) & 1) * 8;
#pragma unroll
                for (int ng = 0; ng < 2; ng++) {
                    LDSM_X4(bh[ng], smem_u32(SB(cur, 0) + (wn + ng * 16 + nr) * SSTR + kk));
                    if (x3) LDSM_X4(bl[ng], smem_u32(SB(cur, 1) + (wn + ng * 16 + nr) * SSTR + kk));
                }
            }
#pragma unroll
            for (int mi = 0; mi < 4; mi++)
#pragma unroll
                for (int ni = 0; ni < 4; ni++) {
                    uint32_t* bH = &bh[ni >> 1][(ni & 1) * 2];
                    MMA_BF16(c[mi][ni], ah[mi], bH);
                    if (x3) {
                        uint32_t* bL = &bl[ni >> 1][(ni & 1) * 2];
                        MMA_BF16(c[mi][ni], ah[mi], bL);
                        MMA_BF16(c[mi][ni], al[mi], bH);
                    }
                }
        }
        __syncthreads();
    }

    const int mrow = m0 + wm + (lane >> 2);
    const int ncol = n0 + wn + 2 * (lane & 3);
#pragma unroll
    for (int mi = 0; mi < 4; mi++) {
#pragma unroll
        for (int ni = 0; ni < 4; ni++) {
            const int col = ncol + ni * 8;
            float v[4];
#pragma unroll
            for (int e = 0; e < 4; e++) {
                float t = c[mi][ni][e] + bias[col + (e & 1)];
                if (ep >= 1) t = (t > 0.f) ? (t + 1.f) : __expf(t);
                if (ep == 2) t = sqrtf(fmaxf(t, 1e-24f));
                v[e] = t;
            }
            const size_t i0 = (size_t)(mrow + mi * 16) * 256 + col;
            const size_t i1 = (size_t)(mrow + mi * 16 + 8) * 256 + col;
            if (obf) {
                uint32_t h0 = packh(v[0], v[1]), h1 = packh(v[2], v[3]);
                *(uint32_t*)&Yh[i0] = h0;
                *(uint32_t*)&Yh[i1] = h1;
                if (obf == 1) {
                    *(uint32_t*)&Yl[i0] = packl(v[0], v[1], h0);
                    *(uint32_t*)&Yl[i1] = packl(v[2], v[3], h1);
                }
            } else {
                *(float2*)(Y + i0) = make_float2(v[0], v[1]);
                *(float2*)(Y + i1) = make_float2(v[2], v[3]);
            }
        }
    }
#undef SA
#undef SB
}

// ---------------------------------------------------------------------------
// Row scalars from bf16 hi/lo
// ---------------------------------------------------------------------------
__global__ __launch_bounds__(256)
void rowsum_kernel(const __nv_bfloat16* __restrict__ Mh, const __nv_bfloat16* __restrict__ Ml,
                   const __nv_bfloat16* __restrict__ Sh, const __nv_bfloat16* __restrict__ Sl,
                   float* __restrict__ A)
{
    const int w    = (blockIdx.x * blockDim.x + threadIdx.x) >> 5;
    const int lane = threadIdx.x & 31;
    const int s  = w & 511;
    const int bh = w >> 9;
    const int b  = bh >> 2, h = bh & 3;
    const size_t base = ((size_t)(b * 512 + s) * 256) + h * 64 + lane * 2;
    float2 mh = __bfloat1622float2(*(const __nv_bfloat162*)&Mh[base]);
    float2 ml = __bfloat1622float2(*(const __nv_bfloat162*)&Ml[base]);
    float2 sh = __bfloat1622float2(*(const __nv_bfloat162*)&Sh[base]);
    float2 sl = __bfloat1622float2(*(const __nv_bfloat162*)&Sl[base]);
    float m0 = mh.x + ml.x, m1 = mh.y + ml.y;
    float s0 = sh.x + sl.x, s1 = sh.y + sl.y;
    float sum = m0 * m0 + m1 * m1 + s0 * s0 + s1 * s1;
#pragma unroll
    for (int o = 16; o; o >>= 1) sum += __shfl_xor_sync(~0u, sum, o);
    if (!lane) A[w] = sum;
}

// ---------------------------------------------------------------------------
// Tensor-core attention (R10 version, measured 1012 us total):
//  - Q fragments hoisted to registers (kt-invariant)
//  - K double-buffered in the smem Q vacates: 1 sync + 1 cp_wait per kt
//  - immediate epilogue (exp/mask/store inside each kt)
//  - Phase C: V double-buffered
// ---------------------------------------------------------------------------
#define SC_STR 516
#define QS 136
#define VS 72
#define BFREG_BYTES 69632
#define ATT_SMEM_BYTES ((640 + 64*SC_STR) * 4 + BFREG_BYTES)   // 204288

__global__ __launch_bounds__(256)
void attn_tc(const float* __restrict__ mask, float* __restrict__ probs)
{
    extern __shared__ __align__(16) float sm[];
    float* aqs   = sm;
    float* aks   = sm + 64;
    float* invzs = sm + 576;
    float* Ssc   = sm + 640;
    __nv_bfloat16* bfr = (__nv_bfloat16*)(sm + 640 + 64 * SC_STR);
    __nv_bfloat16* Khi0 = bfr;
    __nv_bfloat16* Klo0 = bfr + 64 * QS;
    __nv_bfloat16* Khi1 = bfr + 2 * 64 * QS;
    __nv_bfloat16* Klo1 = bfr + 3 * 64 * QS;
    __nv_bfloat16* Phi  = bfr;
    __nv_bfloat16* P2hi = bfr + 64 * VS;
    __nv_bfloat16* Vmh0 = bfr + 2 * 64 * VS;
    __nv_bfloat16* Vch0 = bfr + 3 * 64 * VS;
    __nv_bfloat16* Vmh1 = bfr + 4 * 64 * VS;
    __nv_bfloat16* Vch1 = bfr + 5 * 64 * VS;

    const int tid  = threadIdx.x;
    const int wid  = tid >> 5;
    const int lane = tid & 31;
    const int g    = lane >> 2;
    const int t    = lane & 3;
    const int q0   = blockIdx.x * 64;
    const int h    = blockIdx.y;
    const int b    = blockIdx.z;
    const int wm2  = (wid & 1) * 32;
    const int wn   = (wid >> 1) * 16;

    const float* mrow = mask + ((size_t)b * 512 + q0) * 512;

    auto issueK = [&](int kt, __nv_bfloat16* KH, __nv_bfloat16* KL) {
#pragma unroll
        for (int u = 0; u < 4; u++) {
            int idx = u * 256 + tid;
            int row = idx >> 4;
            int c8  = (idx & 15) * 8;
            const size_t src = ((size_t)(b * 512 + kt * 64 + row) * 256) + h * 64
                             + (c8 < 64 ? c8 : c8 - 64);
            const __nv_bfloat16* ph = (c8 < 64) ? g_mkh : g_skh;
            const __nv_bfloat16* pl = (c8 < 64) ? g_mkl : g_skl;
            cp16(smem_u32(&KH[row * QS + c8]), ph + src);
            cp16(smem_u32(&KL[row * QS + c8]), pl + src);
        }
        CP_COMMIT();
    };
    auto issueV = [&](int kt, __nv_bfloat16* VM, __nv_bfloat16* VC) {
#pragma unroll
        for (int u = 0; u < 2; u++) {
            int idx = u * 256 + tid;
            int row = idx >> 3;
            int d8  = (idx & 7) * 8;
            const size_t src = ((size_t)(b * 512 + kt * 64 + row) * 256) + h * 64 + d8;
            cp16(smem_u32(&VM[row * VS + d8]), g_mvh + src);
            cp16(smem_u32(&VC[row * VS + d8]), g_cvh + src);
        }
        CP_COMMIT();
    };

    if (tid < 64) aqs[tid] = g_aq[(b * 4 + h) * 512 + q0 + tid];
    aks[tid]       = g_ak[(b * 4 + h) * 512 + tid];
    aks[tid + 256] = g_ak[(b * 4 + h) * 512 + 256 + tid];

    issueK(0, Khi0, Klo0);

    // ---- stage Q in buf1 ----
#pragma unroll
    for (int u = 0; u < 4; u++) {
        int idx = u * 256 + tid;
        int row = idx >> 4;
        int c8  = (idx & 15) * 8;
        const size_t src = ((size_t)(b * 512 + q0 + row) * 256) + h * 64
                         + (c8 < 64 ? c8 : c8 - 64);
        const __nv_bfloat16* ph = (c8 < 64) ? g_mqh : g_sqh;
        const __nv_bfloat16* pl = (c8 < 64) ? g_mql : g_sql;
        *(uint4*)&Khi1[row * QS + c8] = *(const uint4*)(ph + src);
        *(uint4*)&Klo1[row * QS + c8] = *(const uint4*)(pl + src);
    }
    __syncthreads();

    // ---- hoist Q fragments to registers (kt-invariant) ----
    uint32_t qfh[8][2][4], qfl[8][2][4];
    {
        const int ar = wm2 + (lane & 15);
#pragma unroll
        for (int ks = 0; ks < 8; ks++) {
            const int akk = ks * 16 + (lane >> 4) * 8;
#pragma unroll
            for (int mi = 0; mi < 2; mi++) {
                LDSM_X4(qfh[ks][mi], smem_u32(&Khi1[(ar + mi * 16) * QS + akk]));
                LDSM_X4(qfl[ks][mi], smem_u32(&Klo1[(ar + mi * 16) * QS + akk]));
            }
        }
    }

    // ================= Phase A =================
    for (int kt = 0; kt < 8; kt++) {
        cp_wait<0>();                          // K(kt) landed
        __syncthreads();                       // visible; prior buf reads done
        __nv_bfloat16* KH = (kt & 1) ? Khi1 : Khi0;
        __nv_bfloat16* KL = (kt & 1) ? Klo1 : Klo0;
        if (kt < 7) issueK(kt + 1, (kt & 1) ? Khi0 : Khi1, (kt & 1) ? Klo0 : Klo1);

        float acc[2][2][4], acl[2][2][4], acm[2][2][4];
#pragma unroll
        for (int mi = 0; mi < 2; mi++)
#pragma unroll
            for (int ni = 0; ni < 2; ni++)
#pragma unroll
                for (int e = 0; e < 4; e++) {
                    acc[mi][ni][e] = 0.f; acl[mi][ni][e] = 0.f; acm[mi][ni][e] = 0.f;
                }

#pragma unroll
        for (int ks = 0; ks < 8; ks++) {
            uint32_t bh[4], bl[4];
            const int nr  = (lane & 7) + ((lane >> 4) & 1) * 8;
            const int kk2 = ks * 16 + ((lane >> 3) & 1) * 8;
            LDSM_X4(bh, smem_u32(&KH[(wn + nr) * QS + kk2]));
            LDSM_X4(bl, smem_u32(&KL[(wn + nr) * QS + kk2]));
#pragma unroll
            for (int mi = 0; mi < 2; mi++)
#pragma unroll
                for (int ni = 0; ni < 2; ni++) {
                    MMA_BF16(acc[mi][ni], qfh[ks][mi], (&bh[ni * 2]));
                    MMA_BF16(acl[mi][ni], qfh[ks][mi], (&bl[ni * 2]));
                    MMA_BF16(acm[mi][ni], qfl[ks][mi], (&bh[ni * 2]));
                }
        }

        // epilogue: dist -> e into Ssc (mask direct from gmem)
#pragma unroll
        for (int mi = 0; mi < 2; mi++) {
            const int i0 = wm2 + mi * 16 + g;
#pragma unroll
            for (int ni = 0; ni < 2; ni++) {
                const int j = kt * 64 + wn + ni * 8 + 2 * t;
                const float akj0 = aks[j], akj1 = aks[j + 1];
                float2 m0 = *(const float2*)&mrow[(size_t)i0 * 512 + j];
                float2 m1 = *(const float2*)&mrow[(size_t)(i0 + 8) * 512 + j];
                float s00 = acc[mi][ni][0] + acl[mi][ni][0] + acm[mi][ni][0];
                float s01 = acc[mi][ni][1] + acl[mi][ni][1] + acm[mi][ni][1];
                float s10 = acc[mi][ni][2] + acl[mi][ni][2] + acm[mi][ni][2];
                float s11 = acc[mi][ni][3] + acl[mi][ni][3] + acm[mi][ni][3];
                float d00 = aqs[i0]     + akj0 - 2.f * s00;
                float d01 = aqs[i0]     + akj1 - 2.f * s01;
                float d10 = aqs[i0 + 8] + akj0 - 2.f * s10;
                float d11 = aqs[i0 + 8] + akj1 - 2.f * s11;
                *(float2*)&Ssc[i0 * SC_STR + j] =
                    make_float2(fexp(-d00) * 0.125f + m0.x, fexp(-d01) * 0.125f + m0.y);
                *(float2*)&Ssc[(i0 + 8) * SC_STR + j] =
                    make_float2(fexp(-d10) * 0.125f + m1.x, fexp(-d11) * 0.125f + m1.y);
            }
        }
    }
    __syncthreads();

    // ================= Phase B: softmax =================
    {
        const int row = tid >> 2, sub = tid & 3;
        float m = -3.0e38f;
        for (int k = sub; k < 512; k += 4) m = fmaxf(m, Ssc[row * SC_STR + k]);
        m = fmaxf(m, __shfl_xor_sync(~0u, m, 1));
        m = fmaxf(m, __shfl_xor_sync(~0u, m, 2));
        float s = 0.f;
        for (int k = sub; k < 512; k += 4) {
            float e = fexp(Ssc[row * SC_STR + k] - m);
            Ssc[row * SC_STR + k] = e;
            s += e;
        }
        s += __shfl_xor_sync(~0u, s, 1);
        s += __shfl_xor_sync(~0u, s, 2);
        if (sub == 0) invzs[row] = 1.f / s;
    }
    __syncthreads();

    issueV(0, Vmh0, Vch0);   // overlaps probs normalize+write

    {
        const size_t pbase = (((size_t)(b * 4 + h)) * 512 + q0) * 512;
#pragma unroll
        for (int u = 0; u < 32; u++) {
            int lin = u * 256 + tid;
            int i   = lin >> 7;
            int k4  = (lin & 127) << 2;
            float z = invzs[i];
            float4 p = *(float4*)&Ssc[i * SC_STR + k4];
            p.x *= z; p.y *= z; p.z *= z; p.w *= z;
            *(float4*)&Ssc[i * SC_STR + k4] = p;
            *(float4*)(probs + pbase + (size_t)i * 512 + k4) = p;
        }
    }

    // ================= Phase C: PV (bf16x1, V double-buffered) =================
    float am[2][2][4], ac2[2][2][4];
#pragma unroll
    for (int mi = 0; mi < 2; mi++)
#pragma unroll
        for (int ni = 0; ni < 2; ni++)
#pragma unroll
            for (int e = 0; e < 4; e++) { am[mi][ni][e] = 0.f; ac2[mi][ni][e] = 0.f; }

    for (int kt = 0; kt < 8; kt++) {
        __syncthreads();                       // prior P/V-alt reads done
#pragma unroll
        for (int u = 0; u < 8; u++) {
            int idx = u * 256 + tid;
            int row = idx >> 5;
            int cp  = (idx & 31) * 2;
            float2 p = *(const float2*)&Ssc[row * SC_STR + kt * 64 + cp];
            *(uint32_t*)&Phi[row * VS + cp]  = packh(p.x, p.y);
            *(uint32_t*)&P2hi[row * VS + cp] = packh(p.x * p.x, p.y * p.y);
        }
        cp_wait<0>();                          // V(kt) landed
        __syncthreads();                       // P + V visible
        __nv_bfloat16* VM = (kt & 1) ? Vmh1 : Vmh0;
        __nv_bfloat16* VC = (kt & 1) ? Vch1 : Vch0;
        if (kt < 7) issueV(kt + 1, (kt & 1) ? Vmh0 : Vmh1, (kt & 1) ? Vch0 : Vch1);

#pragma unroll
        for (int ks = 0; ks < 4; ks++) {
            const int s0 = ks * 16;
            uint32_t ph[2][4], qh[2][4];
            const int ar = wm2 + (lane & 15);
            const int ac = s0 + (lane >> 4) * 8;
#pragma unroll
            for (int mi = 0; mi < 2; mi++) {
                LDSM_X4(ph[mi], smem_u32(&Phi [(ar + mi * 16) * VS + ac]));
                LDSM_X4(qh[mi], smem_u32(&P2hi[(ar + mi * 16) * VS + ac]));
            }
            uint32_t bmh[4], bch[4];
            const int sr = (lane & 7) + ((lane >> 3) & 1) * 8;
            const int d8 = (lane >> 4) * 8;
            const int vbase = (s0 + sr) * VS + wn + d8;
            LDSM_X4_T(bmh, smem_u32(&VM[vbase]));
            LDSM_X4_T(bch, smem_u32(&VC[vbase]));
#pragma unroll
            for (int mi = 0; mi < 2; mi++)
#pragma unroll
                for (int ni = 0; ni < 2; ni++) {
                    MMA_BF16(am[mi][ni],  ph[mi], (&bmh[ni * 2]));
                    MMA_BF16(ac2[mi][ni], qh[mi], (&bch[ni * 2]));
                }
        }
    }

    // ---- store ctx (hi only) ----
#pragma unroll
    for (int mi = 0; mi < 2; mi++) {
#pragma unroll
        for (int ni = 0; ni < 2; ni++) {
            const int row = q0 + wm2 + mi * 16 + g;
            const int col = h * 64 + wn + ni * 8 + 2 * t;
            const size_t i0 = ((size_t)(b * 512 + row)) * 256 + col;
            const size_t i1 = ((size_t)(b * 512 + row + 8)) * 256 + col;
            *(uint32_t*)&g_cmh[i0] = packh(am[mi][ni][0], am[mi][ni][1]);
            *(uint32_t*)&g_cmh[i1] = packh(am[mi][ni][2], am[mi][ni][3]);
            *(uint32_t*)&g_cch[i0] = packh(ac2[mi][ni][0], ac2[mi][ni][1]);
            *(uint32_t*)&g_cch[i1] = packh(ac2[mi][ni][2], ac2[mi][ni][3]);
        }
    }
}

// ---------------------------------------------------------------------------
// LayerNorm: warp-per-row (8 rows per block)
// ---------------------------------------------------------------------------
__global__ __launch_bounds__(256)
void ln_kernel(const float* __restrict__ D, const float* __restrict__ X,
               const float* __restrict__ lw, const float* __restrict__ lb,
               float* __restrict__ O)
{
    const int warp = threadIdx.x >> 5, lane = threadIdx.x & 31;
    const int r = blockIdx.x * 8 + warp;
    const size_t base = (size_t)r * 256 + lane * 8;
    float4 d0 = *(const float4*)(D + base);
    float4 d1 = *(const float4*)(D + base + 4);
    float4 x0 = *(const float4*)(X + base);
    float4 x1 = *(const float4*)(X + base + 4);
    float v[8] = {d0.x + x0.x, d0.y + x0.y, d0.z + x0.z, d0.w + x0.w,
                  d1.x + x1.x, d1.y + x1.y, d1.z + x1.z, d1.w + x1.w};
    float s1 = 0.f, s2 = 0.f;
#pragma unroll
    for (int e = 0; e < 8; e++) { s1 += v[e]; s2 += v[e] * v[e]; }
#pragma unroll
    for (int o = 16; o; o >>= 1) {
        s1 += __shfl_xor_sync(~0u, s1, o);
        s2 += __shfl_xor_sync(~0u, s2, o);
    }
    float u   = s1 * (1.f / 256.f);
    float var = fmaxf(s2 * (1.f / 256.f) - u * u, 0.f);
    float is  = rsqrtf(var + 1e-12f);
    float y[8];
#pragma unroll
    for (int e = 0; e < 8; e++)
        y[e] = fmaf(lw[lane * 8 + e], (v[e] - u) * is, lb[lane * 8 + e]);
    *(float4*)(O + base)     = make_float4(y[0], y[1], y[2], y[3]);
    *(float4*)(O + base + 4) = make_float4(y[4], y[5], y[6], y[7]);
}

// ---------------------------------------------------------------------------
// kernel_launch
// ---------------------------------------------------------------------------
extern "C" void kernel_launch(void* const* d_in, const int* in_sizes, int n_in,
                              void* d_out, int out_size)
{
    (void)in_sizes; (void)n_in; (void)out_size;
    const float* in_mean = (const float*)d_in[0];
    const float* in_cov  = (const float*)d_in[1];
    const float* mask    = (const float*)d_in[2];
    const float* W[8]    = { (const float*)d_in[3],  (const float*)d_in[5],
                             (const float*)d_in[7],  (const float*)d_in[9],
                             (const float*)d_in[11], (const float*)d_in[13],
                             (const float*)d_in[15], (const float*)d_in[17] };
    const float* bia[8]  = { (const float*)d_in[4],  (const float*)d_in[6],
                             (const float*)d_in[8],  (const float*)d_in[10],
                             (const float*)d_in[12], (const float*)d_in[14],
                             (const float*)d_in[16], (const float*)d_in[18] };
    const float* lw  = (const float*)d_in[19];
    const float* lb  = (const float*)d_in[20];
    float* out = (float*)d_out;

    float *dm, *dc, *aq, *ak;
    cudaGetSymbolAddress((void**)&dm, g_dm);
    cudaGetSymbolAddress((void**)&dc, g_dc);
    cudaGetSymbolAddress((void**)&aq, g_aq);
    cudaGetSymbolAddress((void**)&ak, g_ak);

    __nv_bfloat16 *xmh, *xml, *xch, *xcl, *cmh, *cml, *cch, *ccl, *wh, *wl;
    __nv_bfloat16 *mqh, *mql, *mkh, *mkl, *mvh, *mvl, *sqh, *sql, *skh, *skl, *cvh, *cvl;
    cudaGetSymbolAddress((void**)&xmh, g_xmh);  cudaGetSymbolAddress((void**)&xml, g_xml);
    cudaGetSymbolAddress((void**)&xch, g_xch);  cudaGetSymbolAddress((void**)&xcl, g_xcl);
    cudaGetSymbolAddress((void**)&cmh, g_cmh);  cudaGetSymbolAddress((void**)&cml, g_cml);
    cudaGetSymbolAddress((void**)&cch, g_cch);  cudaGetSymbolAddress((void**)&ccl, g_ccl);
    cudaGetSymbolAddress((void**)&wh,  g_wh);   cudaGetSymbolAddress((void**)&wl,  g_wl);
    cudaGetSymbolAddress((void**)&mqh, g_mqh);  cudaGetSymbolAddress((void**)&mql, g_mql);
    cudaGetSymbolAddress((void**)&mkh, g_mkh);  cudaGetSymbolAddress((void**)&mkl, g_mkl);
    cudaGetSymbolAddress((void**)&mvh, g_mvh);  cudaGetSymbolAddress((void**)&mvl, g_mvl);
    cudaGetSymbolAddress((void**)&sqh, g_sqh);  cudaGetSymbolAddress((void**)&sql, g_sql);
    cudaGetSymbolAddress((void**)&skh, g_skh);  cudaGetSymbolAddress((void**)&skl, g_skl);
    cudaGetSymbolAddress((void**)&cvh, g_cvh);  cudaGetSymbolAddress((void**)&cvl, g_cvl);

    cudaFuncSetAttribute(attn_tc, cudaFuncAttributeMaxDynamicSharedMemorySize,
                         ATT_SMEM_BYTES);
    cudaFuncSetAttribute(gemm_hmma, cudaFuncAttributeMaxDynamicSharedMemorySize,
                         GEMM_SMEM);

    // ---- input/weight splits ----
    split_bf16<<<MAT / 4 / 256, 256>>>(in_mean, xmh, xml, MAT / 4);
    split_bf16<<<MAT / 4 / 256, 256>>>(in_cov,  xch, xcl, MAT / 4);
    split_w8<<<dim3(WSZ / 4 / 256, 8), 256>>>(W[0], W[1], W[2], W[3],
                                              W[4], W[5], W[6], W[7], wh, wl);

    dim3 gg1(MROWS / 128, 2, 1);
    dim3 gg2(MROWS / 128, 2, 2);

    // ---- projections: paired launches (share A panel) ----
    gemm_hmma<<<gg2, 256, GEMM_SMEM>>>(xmh, xml, wh + 0*WSZ, wl + 0*WSZ,
                                       bia[0], bia[1], nullptr,
                                       mqh, mql, mkh, mkl, 0, 1, 1);
    gemm_hmma<<<gg2, 256, GEMM_SMEM>>>(xch, xcl, wh + 3*WSZ, wl + 3*WSZ,
                                       bia[3], bia[4], nullptr,
                                       sqh, sql, skh, skl, 2, 1, 1);
    gemm_hmma<<<gg1, 256, GEMM_SMEM>>>(xmh, xml, wh + 2*WSZ, wl + 2*WSZ,
                                       bia[2], bia[2], nullptr,
                                       mvh, mvl, nullptr, nullptr, 0, 2, 0);
    gemm_hmma<<<gg1, 256, GEMM_SMEM>>>(xch, xcl, wh + 5*WSZ, wl + 5*WSZ,
                                       bia[5], bia[5], nullptr,
                                       cvh, cvl, nullptr, nullptr, 1, 2, 0);

    // ---- row scalars ----
    rowsum_kernel<<<NROW / 8, 256>>>(mqh, mql, sqh, sql, aq);
    rowsum_kernel<<<NROW / 8, 256>>>(mkh, mkl, skh, skl, ak);

    // ---- tensor-core attention ----
    attn_tc<<<dim3(SS / 64, NH, BB), 256, ATT_SMEM_BYTES>>>(mask, out + 2 * (size_t)MAT);

    // ---- output denses (x1, fp32 out) ----
    gemm_hmma<<<gg1, 256, GEMM_SMEM>>>(cmh, cml, wh + 6*WSZ, wl + 6*WSZ,
                                       bia[6], bia[6], dm,
                                       nullptr, nullptr, nullptr, nullptr, 0, 0, 0);
    gemm_hmma<<<gg1, 256, GEMM_SMEM>>>(cch, ccl, wh + 7*WSZ, wl + 7*WSZ,
                                       bia[7], bia[7], dc,
                                       nullptr, nullptr, nullptr, nullptr, 0, 0, 0);

    // ---- residual + layernorm ----
    ln_kernel<<<MROWS / 8, 256>>>(dm, in_mean, lw, lb, out);
    ln_kernel<<<MROWS / 8, 256>>>(dc, in_cov,  lw, lb, out + (size_t)MAT);
}

// round 15
// speedup vs baseline: 1.0972x; 1.0356x over previous
#include <cuda_runtime.h>
#include <cuda_bf16.h>
#include <stdint.h>
#include <math.h>

// ---------------------------------------------------------------------------
// Problem constants
// ---------------------------------------------------------------------------
#define BB   64
#define SS   512
#define HID  256
#define NH   4
#define DH   64
#define MROWS (BB*SS)            // 32768
#define MAT   (MROWS*HID)        // 8388608
#define NROW  (BB*NH*SS)         // 131072
#define WSZ   (HID*HID)          // 65536

// ---------------------------------------------------------------------------
// Scratch (device globals; no allocation allowed)
// ---------------------------------------------------------------------------
__device__ float g_dm[MAT];
__device__ float g_dc[MAT];
__device__ float g_aq[NROW];
__device__ float g_ak[NROW];
__device__ __nv_bfloat16 g_xmh[MAT], g_xml[MAT];
__device__ __nv_bfloat16 g_xch[MAT], g_xcl[MAT];
__device__ __nv_bfloat16 g_cmh[MAT], g_cml[MAT];
__device__ __nv_bfloat16 g_cch[MAT], g_ccl[MAT];
__device__ __nv_bfloat16 g_wh[8*WSZ], g_wl[8*WSZ];
__device__ __nv_bfloat16 g_mqh[MAT], g_mql[MAT];
__device__ __nv_bfloat16 g_mkh[MAT], g_mkl[MAT];
__device__ __nv_bfloat16 g_mvh[MAT], g_mvl[MAT];
__device__ __nv_bfloat16 g_sqh[MAT], g_sql[MAT];
__device__ __nv_bfloat16 g_skh[MAT], g_skl[MAT];
__device__ __nv_bfloat16 g_cvh[MAT], g_cvl[MAT];

// ---------------------------------------------------------------------------
// Helpers
// ---------------------------------------------------------------------------
__device__ __forceinline__ uint32_t smem_u32(const void* p) {
    uint32_t a;
    asm("{ .reg .u64 t; cvta.to.shared.u64 t, %1; cvt.u32.u64 %0, t; }"
        : "=r"(a) : "l"(p));
    return a;
}

#define LDSM_X4(d, addr) \
    asm volatile("ldmatrix.sync.aligned.m8n8.x4.shared.b16 {%0,%1,%2,%3}, [%4];" \
        : "=r"((d)[0]), "=r"((d)[1]), "=r"((d)[2]), "=r"((d)[3]) : "r"(addr))

#define LDSM_X4_T(d, addr) \
    asm volatile("ldmatrix.sync.aligned.m8n8.x4.trans.shared.b16 {%0,%1,%2,%3}, [%4];" \
        : "=r"((d)[0]), "=r"((d)[1]), "=r"((d)[2]), "=r"((d)[3]) : "r"(addr))

#define MMA_BF16(c, a, b) \
    asm volatile("mma.sync.aligned.m16n8k16.row.col.f32.bf16.bf16.f32 " \
        "{%0,%1,%2,%3}, {%4,%5,%6,%7}, {%8,%9}, {%0,%1,%2,%3};" \
        : "+f"((c)[0]), "+f"((c)[1]), "+f"((c)[2]), "+f"((c)[3]) \
        : "r"((a)[0]), "r"((a)[1]), "r"((a)[2]), "r"((a)[3]), \
          "r"((b)[0]), "r"((b)[1]))

__device__ __forceinline__ void cp16(uint32_t saddr, const void* g) {
    asm volatile("cp.async.cg.shared.global [%0], [%1], 16;" :: "r"(saddr), "l"(g));
}
#define CP_COMMIT() asm volatile("cp.async.commit_group;")
template<int N> __device__ __forceinline__ void cp_wait() {
    asm volatile("cp.async.wait_group %0;" :: "n"(N));
}

__device__ __forceinline__ uint32_t packh(float x, float y) {
    __nv_bfloat162 r; r.x = __float2bfloat16(x); r.y = __float2bfloat16(y);
    return *(uint32_t*)&r;
}
__device__ __forceinline__ uint32_t packl(float x, float y, uint32_t hp) {
    __nv_bfloat162 h = *(__nv_bfloat162*)&hp;
    __nv_bfloat162 r;
    r.x = __float2bfloat16(x - __bfloat162float(h.x));
    r.y = __float2bfloat16(y - __bfloat162float(h.y));
    return *(uint32_t*)&r;
}

// Fast exp (FFMA pipe). |rel err| ~3e-6.
__device__ __forceinline__ float fexp(float x) {
    x = fmaxf(fminf(x, 80.f), -87.f);
    float y = x * 1.4426950408889634f;
    int   i = __float2int_rn(y);
    float f = y - (float)i;
    float p = 1.3333558146e-3f;
    p = fmaf(p, f, 9.6181291918e-3f);
    p = fmaf(p, f, 5.5504108664e-2f);
    p = fmaf(p, f, 2.4022650696e-1f);
    p = fmaf(p, f, 6.9314718056e-1f);
    p = fmaf(p, f, 1.0f);
    return __int_as_float(__float_as_int(p) + (i << 23));
}

// ---------------------------------------------------------------------------
// fp32 -> bf16 hi/lo splits
// ---------------------------------------------------------------------------
__global__ __launch_bounds__(256)
void split_bf16(const float* __restrict__ x, __nv_bfloat16* __restrict__ hi,
                __nv_bfloat16* __restrict__ lo, int n4)
{
    int i = blockIdx.x * 256 + threadIdx.x;
    if (i >= n4) return;
    float4 v = ((const float4*)x)[i];
    uint32_t h0 = packh(v.x, v.y), h1 = packh(v.z, v.w);
    ((uint32_t*)hi)[i * 2]     = h0;
    ((uint32_t*)hi)[i * 2 + 1] = h1;
    ((uint32_t*)lo)[i * 2]     = packl(v.x, v.y, h0);
    ((uint32_t*)lo)[i * 2 + 1] = packl(v.z, v.w, h1);
}

__global__ __launch_bounds__(256)
void split_w8(const float* __restrict__ w0, const float* __restrict__ w1,
              const float* __restrict__ w2, const float* __restrict__ w3,
              const float* __restrict__ w4, const float* __restrict__ w5,
              const float* __restrict__ w6, const float* __restrict__ w7,
              __nv_bfloat16* __restrict__ hi, __nv_bfloat16* __restrict__ lo)
{
    const float* ws[8] = {w0, w1, w2, w3, w4, w5, w6, w7};
    const int z = blockIdx.y;
    const float* x = ws[z];
    int i = blockIdx.x * 256 + threadIdx.x;
    float4 v = ((const float4*)x)[i];
    uint32_t h0 = packh(v.x, v.y), h1 = packh(v.z, v.w);
    size_t o = (size_t)z * WSZ / 4 + i;
    ((uint32_t*)hi)[o * 2]     = h0;
    ((uint32_t*)hi)[o * 2 + 1] = h1;
    ((uint32_t*)lo)[o * 2]     = packl(v.x, v.y, h0);
    ((uint32_t*)lo)[o * 2 + 1] = packl(v.z, v.w, h1);
}

// ---------------------------------------------------------------------------
// HMMA GEMM, fully paired via blockIdx.z: z selects A, B, bias, output and
// epilogue. Lets any two GEMMs run in one launch (wave-quantization win).
// ---------------------------------------------------------------------------
#define SSTR 40
#define GEMM_SMEM (8 * 128 * SSTR * 2)

__global__ __launch_bounds__(256)
void gemm_hmma(const __nv_bfloat16* __restrict__ AhA, const __nv_bfloat16* __restrict__ AlA,
               const __nv_bfloat16* __restrict__ AhB, const __nv_bfloat16* __restrict__ AlB,
               const __nv_bfloat16* __restrict__ BhA, const __nv_bfloat16* __restrict__ BlA,
               const __nv_bfloat16* __restrict__ BhB, const __nv_bfloat16* __restrict__ BlB,
               const float* __restrict__ biasA, const float* __restrict__ biasB,
               float* __restrict__ YA, float* __restrict__ YB,
               __nv_bfloat16* __restrict__ YhA, __nv_bfloat16* __restrict__ YlA,
               __nv_bfloat16* __restrict__ YhB, __nv_bfloat16* __restrict__ YlB,
               int epA, int epB, int obf, int x3)
{
    extern __shared__ __align__(16) __nv_bfloat16 gsm[];

    const int z = blockIdx.z;
    const __nv_bfloat16* Ah = z ? AhB : AhA;
    const __nv_bfloat16* Al = z ? AlB : AlA;
    const __nv_bfloat16* Bh = z ? BhB : BhA;
    const __nv_bfloat16* Bl = z ? BlB : BlA;
    const float* bias = z ? biasB : biasA;
    float* Y = z ? YB : YA;
    __nv_bfloat16* Yh = z ? YhB : YhA;
    __nv_bfloat16* Yl = z ? YlB : YlA;
    const int ep = z ? epB : epA;

    const int tid  = threadIdx.x;
    const int wid  = tid >> 5;
    const int lane = tid & 31;
    const int m0   = blockIdx.x * 128;
    const int n0   = blockIdx.y * 128;
    const int wm   = (wid & 1) * 64;
    const int wn   = (wid >> 1) * 32;

#define SA(bd, hl) (gsm + ((bd) * 2 + (hl)) * (128 * SSTR))
#define SB(bd, hl) (gsm + (4 + (bd) * 2 + (hl)) * (128 * SSTR))

    float c[4][4][4];
#pragma unroll
    for (int mi = 0; mi < 4; mi++)
#pragma unroll
        for (int ni = 0; ni < 4; ni++)
#pragma unroll
            for (int e = 0; e < 4; e++) c[mi][ni][e] = 0.f;

    auto issue = [&](int kc, int bd) {
#pragma unroll
        for (int u = 0; u < 2; u++) {
            int idx = u * 256 + tid;
            int row = idx >> 2;
            int f4  = idx & 3;
            int soff = row * SSTR + f4 * 8;
            const size_t ga = (size_t)(m0 + row) * 256 + kc * 32 + f4 * 8;
            const size_t gb = (size_t)(n0 + row) * 256 + kc * 32 + f4 * 8;
            cp16(smem_u32(SA(bd, 0) + soff), Ah + ga);
            cp16(smem_u32(SB(bd, 0) + soff), Bh + gb);
            if (x3) {
                cp16(smem_u32(SA(bd, 1) + soff), Al + ga);
                cp16(smem_u32(SB(bd, 1) + soff), Bl + gb);
            }
        }
        CP_COMMIT();
    };

    issue(0, 0);
    for (int kc = 0; kc < 8; kc++) {
        const int cur = kc & 1;
        if (kc < 7) { issue(kc + 1, cur ^ 1); cp_wait<1>(); }
        else        { cp_wait<0>(); }
        __syncthreads();

#pragma unroll
        for (int ks = 0; ks < 2; ks++) {
            const int kb = ks * 16;
            uint32_t ah[4][4], al[4][4];
            {
                const int r  = wm + (lane & 15);
                const int kk = kb + (lane >> 4) * 8;
#pragma unroll
                for (int mi = 0; mi < 4; mi++) {
                    LDSM_X4(ah[mi], smem_u32(SA(cur, 0) + (r + mi * 16) * SSTR + kk));
                    if (x3) LDSM_X4(al[mi], smem_u32(SA(cur, 1) + (r + mi * 16) * SSTR + kk));
                }
            }
            uint32_t bh[2][4], bl[2][4];
            {
                const int nr = (lane & 7) + ((lane >> 4) & 1) * 8;
                const int kk = kb + ((lane >> 3) & 1) * 8;
#pragma unroll
                for (int ng = 0; ng < 2; ng++) {
                    LDSM_X4(bh[ng], smem_u32(SB(cur, 0) + (wn + ng * 16 + nr) * SSTR + kk));
                    if (x3) LDSM_X4(bl[ng], smem_u32(SB(cur, 1) + (wn + ng * 16 + nr) * SSTR + kk));
                }
            }
#pragma unroll
            for (int mi = 0; mi < 4; mi++)
#pragma unroll
                for (int ni = 0; ni < 4; ni++) {
                    uint32_t* bH = &bh[ni >> 1][(ni & 1) * 2];
                    MMA_BF16(c[mi][ni], ah[mi], bH);
                    if (x3) {
                        uint32_t* bL = &bl[ni >> 1][(ni & 1) * 2];
                        MMA_BF16(c[mi][ni], ah[mi], bL);
                        MMA_BF16(c[mi][ni], al[mi], bH);
                    }
                }
        }
        __syncthreads();
    }

    const int mrow = m0 + wm + (lane >> 2);
    const int ncol = n0 + wn + 2 * (lane & 3);
#pragma unroll
    for (int mi = 0; mi < 4; mi++) {
#pragma unroll
        for (int ni = 0; ni < 4; ni++) {
            const int col = ncol + ni * 8;
            float v[4];
#pragma unroll
            for (int e = 0; e < 4; e++) {
                float t = c[mi][ni][e] + bias[col + (e & 1)];
                if (ep >= 1) t = (t > 0.f) ? (t + 1.f) : __expf(t);
                if (ep == 2) t = sqrtf(fmaxf(t, 1e-24f));
                v[e] = t;
            }
            const size_t i0 = (size_t)(mrow + mi * 16) * 256 + col;
            const size_t i1 = (size_t)(mrow + mi * 16 + 8) * 256 + col;
            if (obf) {
                uint32_t h0 = packh(v[0], v[1]), h1 = packh(v[2], v[3]);
                *(uint32_t*)&Yh[i0] = h0;
                *(uint32_t*)&Yh[i1] = h1;
                if (obf == 1) {
                    *(uint32_t*)&Yl[i0] = packl(v[0], v[1], h0);
                    *(uint32_t*)&Yl[i1] = packl(v[2], v[3], h1);
                }
            } else {
                *(float2*)(Y + i0) = make_float2(v[0], v[1]);
                *(float2*)(Y + i1) = make_float2(v[2], v[3]);
            }
        }
    }
#undef SA
#undef SB
}

// ---------------------------------------------------------------------------
// Row scalars from bf16 hi/lo
// ---------------------------------------------------------------------------
__global__ __launch_bounds__(256)
void rowsum_kernel(const __nv_bfloat16* __restrict__ Mh, const __nv_bfloat16* __restrict__ Ml,
                   const __nv_bfloat16* __restrict__ Sh, const __nv_bfloat16* __restrict__ Sl,
                   float* __restrict__ A)
{
    const int w    = (blockIdx.x * blockDim.x + threadIdx.x) >> 5;
    const int lane = threadIdx.x & 31;
    const int s  = w & 511;
    const int bh = w >> 9;
    const int b  = bh >> 2, h = bh & 3;
    const size_t base = ((size_t)(b * 512 + s) * 256) + h * 64 + lane * 2;
    float2 mh = __bfloat1622float2(*(const __nv_bfloat162*)&Mh[base]);
    float2 ml = __bfloat1622float2(*(const __nv_bfloat162*)&Ml[base]);
    float2 sh = __bfloat1622float2(*(const __nv_bfloat162*)&Sh[base]);
    float2 sl = __bfloat1622float2(*(const __nv_bfloat162*)&Sl[base]);
    float m0 = mh.x + ml.x, m1 = mh.y + ml.y;
    float s0 = sh.x + sl.x, s1 = sh.y + sl.y;
    float sum = m0 * m0 + m1 * m1 + s0 * s0 + s1 * s1;
#pragma unroll
    for (int o = 16; o; o >>= 1) sum += __shfl_xor_sync(~0u, sum, o);
    if (!lane) A[w] = sum;
}

// ---------------------------------------------------------------------------
// Tensor-core attention (R10 core). Change vs R14: normalize pass only
// writes probs to gmem (no Ssc write-back); 1/z folded into phase-C P pack.
// ---------------------------------------------------------------------------
#define SC_STR 516
#define QS 136
#define VS 72
#define BFREG_BYTES 69632
#define ATT_SMEM_BYTES ((640 + 64*SC_STR) * 4 + BFREG_BYTES)   // 204288

__global__ __launch_bounds__(256)
void attn_tc(const float* __restrict__ mask, float* __restrict__ probs)
{
    extern __shared__ __align__(16) float sm[];
    float* aqs   = sm;
    float* aks   = sm + 64;
    float* invzs = sm + 576;
    float* Ssc   = sm + 640;
    __nv_bfloat16* bfr = (__nv_bfloat16*)(sm + 640 + 64 * SC_STR);
    __nv_bfloat16* Khi0 = bfr;
    __nv_bfloat16* Klo0 = bfr + 64 * QS;
    __nv_bfloat16* Khi1 = bfr + 2 * 64 * QS;
    __nv_bfloat16* Klo1 = bfr + 3 * 64 * QS;
    __nv_bfloat16* Phi  = bfr;
    __nv_bfloat16* P2hi = bfr + 64 * VS;
    __nv_bfloat16* Vmh0 = bfr + 2 * 64 * VS;
    __nv_bfloat16* Vch0 = bfr + 3 * 64 * VS;
    __nv_bfloat16* Vmh1 = bfr + 4 * 64 * VS;
    __nv_bfloat16* Vch1 = bfr + 5 * 64 * VS;

    const int tid  = threadIdx.x;
    const int wid  = tid >> 5;
    const int lane = tid & 31;
    const int g    = lane >> 2;
    const int t    = lane & 3;
    const int q0   = blockIdx.x * 64;
    const int h    = blockIdx.y;
    const int b    = blockIdx.z;
    const int wm2  = (wid & 1) * 32;
    const int wn   = (wid >> 1) * 16;

    const float* mrow = mask + ((size_t)b * 512 + q0) * 512;

    auto issueK = [&](int kt, __nv_bfloat16* KH, __nv_bfloat16* KL) {
#pragma unroll
        for (int u = 0; u < 4; u++) {
            int idx = u * 256 + tid;
            int row = idx >> 4;
            int c8  = (idx & 15) * 8;
            const size_t src = ((size_t)(b * 512 + kt * 64 + row) * 256) + h * 64
                             + (c8 < 64 ? c8 : c8 - 64);
            const __nv_bfloat16* ph = (c8 < 64) ? g_mkh : g_skh;
            const __nv_bfloat16* pl = (c8 < 64) ? g_mkl : g_skl;
            cp16(smem_u32(&KH[row * QS + c8]), ph + src);
            cp16(smem_u32(&KL[row * QS + c8]), pl + src);
        }
        CP_COMMIT();
    };
    auto issueV = [&](int kt, __nv_bfloat16* VM, __nv_bfloat16* VC) {
#pragma unroll
        for (int u = 0; u < 2; u++) {
            int idx = u * 256 + tid;
            int row = idx >> 3;
            int d8  = (idx & 7) * 8;
            const size_t src = ((size_t)(b * 512 + kt * 64 + row) * 256) + h * 64 + d8;
            cp16(smem_u32(&VM[row * VS + d8]), g_mvh + src);
            cp16(smem_u32(&VC[row * VS + d8]), g_cvh + src);
        }
        CP_COMMIT();
    };

    if (tid < 64) aqs[tid] = g_aq[(b * 4 + h) * 512 + q0 + tid];
    aks[tid]       = g_ak[(b * 4 + h) * 512 + tid];
    aks[tid + 256] = g_ak[(b * 4 + h) * 512 + 256 + tid];

    issueK(0, Khi0, Klo0);

    // ---- stage Q in buf1 ----
#pragma unroll
    for (int u = 0; u < 4; u++) {
        int idx = u * 256 + tid;
        int row = idx >> 4;
        int c8  = (idx & 15) * 8;
        const size_t src = ((size_t)(b * 512 + q0 + row) * 256) + h * 64
                         + (c8 < 64 ? c8 : c8 - 64);
        const __nv_bfloat16* ph = (c8 < 64) ? g_mqh : g_sqh;
        const __nv_bfloat16* pl = (c8 < 64) ? g_mql : g_sql;
        *(uint4*)&Khi1[row * QS + c8] = *(const uint4*)(ph + src);
        *(uint4*)&Klo1[row * QS + c8] = *(const uint4*)(pl + src);
    }
    __syncthreads();

    // ---- hoist Q fragments to registers (kt-invariant) ----
    uint32_t qfh[8][2][4], qfl[8][2][4];
    {
        const int ar = wm2 + (lane & 15);
#pragma unroll
        for (int ks = 0; ks < 8; ks++) {
            const int akk = ks * 16 + (lane >> 4) * 8;
#pragma unroll
            for (int mi = 0; mi < 2; mi++) {
                LDSM_X4(qfh[ks][mi], smem_u32(&Khi1[(ar + mi * 16) * QS + akk]));
                LDSM_X4(qfl[ks][mi], smem_u32(&Klo1[(ar + mi * 16) * QS + akk]));
            }
        }
    }

    // ================= Phase A =================
    for (int kt = 0; kt < 8; kt++) {
        cp_wait<0>();                          // K(kt) landed
        __syncthreads();                       // visible; prior buf reads done
        __nv_bfloat16* KH = (kt & 1) ? Khi1 : Khi0;
        __nv_bfloat16* KL = (kt & 1) ? Klo1 : Klo0;
        if (kt < 7) issueK(kt + 1, (kt & 1) ? Khi0 : Khi1, (kt & 1) ? Klo0 : Klo1);

        float acc[2][2][4], acl[2][2][4], acm[2][2][4];
#pragma unroll
        for (int mi = 0; mi < 2; mi++)
#pragma unroll
            for (int ni = 0; ni < 2; ni++)
#pragma unroll
                for (int e = 0; e < 4; e++) {
                    acc[mi][ni][e] = 0.f; acl[mi][ni][e] = 0.f; acm[mi][ni][e] = 0.f;
                }

#pragma unroll
        for (int ks = 0; ks < 8; ks++) {
            uint32_t bh[4], bl[4];
            const int nr  = (lane & 7) + ((lane >> 4) & 1) * 8;
            const int kk2 = ks * 16 + ((lane >> 3) & 1) * 8;
            LDSM_X4(bh, smem_u32(&KH[(wn + nr) * QS + kk2]));
            LDSM_X4(bl, smem_u32(&KL[(wn + nr) * QS + kk2]));
#pragma unroll
            for (int mi = 0; mi < 2; mi++)
#pragma unroll
                for (int ni = 0; ni < 2; ni++) {
                    MMA_BF16(acc[mi][ni], qfh[ks][mi], (&bh[ni * 2]));
                    MMA_BF16(acl[mi][ni], qfh[ks][mi], (&bl[ni * 2]));
                    MMA_BF16(acm[mi][ni], qfl[ks][mi], (&bh[ni * 2]));
                }
        }

        // epilogue: dist -> e into Ssc (mask direct from gmem)
#pragma unroll
        for (int mi = 0; mi < 2; mi++) {
            const int i0 = wm2 + mi * 16 + g;
#pragma unroll
            for (int ni = 0; ni < 2; ni++) {
                const int j = kt * 64 + wn + ni * 8 + 2 * t;
                const float akj0 = aks[j], akj1 = aks[j + 1];
                float2 m0 = *(const float2*)&mrow[(size_t)i0 * 512 + j];
                float2 m1 = *(const float2*)&mrow[(size_t)(i0 + 8) * 512 + j];
                float s00 = acc[mi][ni][0] + acl[mi][ni][0] + acm[mi][ni][0];
                float s01 = acc[mi][ni][1] + acl[mi][ni][1] + acm[mi][ni][1];
                float s10 = acc[mi][ni][2] + acl[mi][ni][2] + acm[mi][ni][2];
                float s11 = acc[mi][ni][3] + acl[mi][ni][3] + acm[mi][ni][3];
                float d00 = aqs[i0]     + akj0 - 2.f * s00;
                float d01 = aqs[i0]     + akj1 - 2.f * s01;
                float d10 = aqs[i0 + 8] + akj0 - 2.f * s10;
                float d11 = aqs[i0 + 8] + akj1 - 2.f * s11;
                *(float2*)&Ssc[i0 * SC_STR + j] =
                    make_float2(fexp(-d00) * 0.125f + m0.x, fexp(-d01) * 0.125f + m0.y);
                *(float2*)&Ssc[(i0 + 8) * SC_STR + j] =
                    make_float2(fexp(-d10) * 0.125f + m1.x, fexp(-d11) * 0.125f + m1.y);
            }
        }
    }
    __syncthreads();

    // ================= Phase B: softmax =================
    {
        const int row = tid >> 2, sub = tid & 3;
        float m = -3.0e38f;
        for (int k = sub; k < 512; k += 4) m = fmaxf(m, Ssc[row * SC_STR + k]);
        m = fmaxf(m, __shfl_xor_sync(~0u, m, 1));
        m = fmaxf(m, __shfl_xor_sync(~0u, m, 2));
        float s = 0.f;
        for (int k = sub; k < 512; k += 4) {
            float e = fexp(Ssc[row * SC_STR + k] - m);
            Ssc[row * SC_STR + k] = e;
            s += e;
        }
        s += __shfl_xor_sync(~0u, s, 1);
        s += __shfl_xor_sync(~0u, s, 2);
        if (sub == 0) invzs[row] = 1.f / s;
    }
    __syncthreads();

    issueV(0, Vmh0, Vch0);   // overlaps probs write

    // normalize only into gmem probs (Ssc keeps raw exp values)
    {
        const size_t pbase = (((size_t)(b * 4 + h)) * 512 + q0) * 512;
#pragma unroll
        for (int u = 0; u < 32; u++) {
            int lin = u * 256 + tid;
            int i   = lin >> 7;
            int k4  = (lin & 127) << 2;
            float z = invzs[i];
            float4 p = *(float4*)&Ssc[i * SC_STR + k4];
            p.x *= z; p.y *= z; p.z *= z; p.w *= z;
            *(float4*)(probs + pbase + (size_t)i * 512 + k4) = p;
        }
    }

    // ================= Phase C: PV (bf16x1, V double-buffered) =================
    float am[2][2][4], ac2[2][2][4];
#pragma unroll
    for (int mi = 0; mi < 2; mi++)
#pragma unroll
        for (int ni = 0; ni < 2; ni++)
#pragma unroll
            for (int e = 0; e < 4; e++) { am[mi][ni][e] = 0.f; ac2[mi][ni][e] = 0.f; }

    for (int kt = 0; kt < 8; kt++) {
        __syncthreads();                       // prior P/V-alt reads done
#pragma unroll
        for (int u = 0; u < 8; u++) {
            int idx = u * 256 + tid;
            int row = idx >> 5;
            int cp  = (idx & 31) * 2;
            float z = invzs[row];
            float2 p = *(const float2*)&Ssc[row * SC_STR + kt * 64 + cp];
            float px = p.x * z, py = p.y * z;
            *(uint32_t*)&Phi[row * VS + cp]  = packh(px, py);
            *(uint32_t*)&P2hi[row * VS + cp] = packh(px * px, py * py);
        }
        cp_wait<0>();                          // V(kt) landed
        __syncthreads();                       // P + V visible
        __nv_bfloat16* VM = (kt & 1) ? Vmh1 : Vmh0;
        __nv_bfloat16* VC = (kt & 1) ? Vch1 : Vch0;
        if (kt < 7) issueV(kt + 1, (kt & 1) ? Vmh0 : Vmh1, (kt & 1) ? Vch0 : Vch1);

#pragma unroll
        for (int ks = 0; ks < 4; ks++) {
            const int s0 = ks * 16;
            uint32_t ph[2][4], qh[2][4];
            const int ar = wm2 + (lane & 15);
            const int ac = s0 + (lane >> 4) * 8;
#pragma unroll
            for (int mi = 0; mi < 2; mi++) {
                LDSM_X4(ph[mi], smem_u32(&Phi [(ar + mi * 16) * VS + ac]));
                LDSM_X4(qh[mi], smem_u32(&P2hi[(ar + mi * 16) * VS + ac]));
            }
            uint32_t bmh[4], bch[4];
            const int sr = (lane & 7) + ((lane >> 3) & 1) * 8;
            const int d8 = (lane >> 4) * 8;
            const int vbase = (s0 + sr) * VS + wn + d8;
            LDSM_X4_T(bmh, smem_u32(&VM[vbase]));
            LDSM_X4_T(bch, smem_u32(&VC[vbase]));
#pragma unroll
            for (int mi = 0; mi < 2; mi++)
#pragma unroll
                for (int ni = 0; ni < 2; ni++) {
                    MMA_BF16(am[mi][ni],  ph[mi], (&bmh[ni * 2]));
                    MMA_BF16(ac2[mi][ni], qh[mi], (&bch[ni * 2]));
                }
        }
    }

    // ---- store ctx (hi only) ----
#pragma unroll
    for (int mi = 0; mi < 2; mi++) {
#pragma unroll
        for (int ni = 0; ni < 2; ni++) {
            const int row = q0 + wm2 + mi * 16 + g;
            const int col = h * 64 + wn + ni * 8 + 2 * t;
            const size_t i0 = ((size_t)(b * 512 + row)) * 256 + col;
            const size_t i1 = ((size_t)(b * 512 + row + 8)) * 256 + col;
            *(uint32_t*)&g_cmh[i0] = packh(am[mi][ni][0], am[mi][ni][1]);
            *(uint32_t*)&g_cmh[i1] = packh(am[mi][ni][2], am[mi][ni][3]);
            *(uint32_t*)&g_cch[i0] = packh(ac2[mi][ni][0], ac2[mi][ni][1]);
            *(uint32_t*)&g_cch[i1] = packh(ac2[mi][ni][2], ac2[mi][ni][3]);
        }
    }
}

// ---------------------------------------------------------------------------
// LayerNorm: warp-per-row (8 rows per block)
// ---------------------------------------------------------------------------
__global__ __launch_bounds__(256)
void ln_kernel(const float* __restrict__ D, const float* __restrict__ X,
               const float* __restrict__ lw, const float* __restrict__ lb,
               float* __restrict__ O)
{
    const int warp = threadIdx.x >> 5, lane = threadIdx.x & 31;
    const int r = blockIdx.x * 8 + warp;
    const size_t base = (size_t)r * 256 + lane * 8;
    float4 d0 = *(const float4*)(D + base);
    float4 d1 = *(const float4*)(D + base + 4);
    float4 x0 = *(const float4*)(X + base);
    float4 x1 = *(const float4*)(X + base + 4);
    float v[8] = {d0.x + x0.x, d0.y + x0.y, d0.z + x0.z, d0.w + x0.w,
                  d1.x + x1.x, d1.y + x1.y, d1.z + x1.z, d1.w + x1.w};
    float s1 = 0.f, s2 = 0.f;
#pragma unroll
    for (int e = 0; e < 8; e++) { s1 += v[e]; s2 += v[e] * v[e]; }
#pragma unroll
    for (int o = 16; o; o >>= 1) {
        s1 += __shfl_xor_sync(~0u, s1, o);
        s2 += __shfl_xor_sync(~0u, s2, o);
    }
    float u   = s1 * (1.f / 256.f);
    float var = fmaxf(s2 * (1.f / 256.f) - u * u, 0.f);
    float is  = rsqrtf(var + 1e-12f);
    float y[8];
#pragma unroll
    for (int e = 0; e < 8; e++)
        y[e] = fmaf(lw[lane * 8 + e], (v[e] - u) * is, lb[lane * 8 + e]);
    *(float4*)(O + base)     = make_float4(y[0], y[1], y[2], y[3]);
    *(float4*)(O + base + 4) = make_float4(y[4], y[5], y[6], y[7]);
}

// ---------------------------------------------------------------------------
// kernel_launch
// ---------------------------------------------------------------------------
extern "C" void kernel_launch(void* const* d_in, const int* in_sizes, int n_in,
                              void* d_out, int out_size)
{
    (void)in_sizes; (void)n_in; (void)out_size;
    const float* in_mean = (const float*)d_in[0];
    const float* in_cov  = (const float*)d_in[1];
    const float* mask    = (const float*)d_in[2];
    const float* W[8]    = { (const float*)d_in[3],  (const float*)d_in[5],
                             (const float*)d_in[7],  (const float*)d_in[9],
                             (const float*)d_in[11], (const float*)d_in[13],
                             (const float*)d_in[15], (const float*)d_in[17] };
    const float* bia[8]  = { (const float*)d_in[4],  (const float*)d_in[6],
                             (const float*)d_in[8],  (const float*)d_in[10],
                             (const float*)d_in[12], (const float*)d_in[14],
                             (const float*)d_in[16], (const float*)d_in[18] };
    const float* lw  = (const float*)d_in[19];
    const float* lb  = (const float*)d_in[20];
    float* out = (float*)d_out;

    float *dm, *dc, *aq, *ak;
    cudaGetSymbolAddress((void**)&dm, g_dm);
    cudaGetSymbolAddress((void**)&dc, g_dc);
    cudaGetSymbolAddress((void**)&aq, g_aq);
    cudaGetSymbolAddress((void**)&ak, g_ak);

    __nv_bfloat16 *xmh, *xml, *xch, *xcl, *cmh, *cml, *cch, *ccl, *wh, *wl;
    __nv_bfloat16 *mqh, *mql, *mkh, *mkl, *mvh, *mvl, *sqh, *sql, *skh, *skl, *cvh, *cvl;
    cudaGetSymbolAddress((void**)&xmh, g_xmh);  cudaGetSymbolAddress((void**)&xml, g_xml);
    cudaGetSymbolAddress((void**)&xch, g_xch);  cudaGetSymbolAddress((void**)&xcl, g_xcl);
    cudaGetSymbolAddress((void**)&cmh, g_cmh);  cudaGetSymbolAddress((void**)&cml, g_cml);
    cudaGetSymbolAddress((void**)&cch, g_cch);  cudaGetSymbolAddress((void**)&ccl, g_ccl);
    cudaGetSymbolAddress((void**)&wh,  g_wh);   cudaGetSymbolAddress((void**)&wl,  g_wl);
    cudaGetSymbolAddress((void**)&mqh, g_mqh);  cudaGetSymbolAddress((void**)&mql, g_mql);
    cudaGetSymbolAddress((void**)&mkh, g_mkh);  cudaGetSymbolAddress((void**)&mkl, g_mkl);
    cudaGetSymbolAddress((void**)&mvh, g_mvh);  cudaGetSymbolAddress((void**)&mvl, g_mvl);
    cudaGetSymbolAddress((void**)&sqh, g_sqh);  cudaGetSymbolAddress((void**)&sql, g_sql);
    cudaGetSymbolAddress((void**)&skh, g_skh);  cudaGetSymbolAddress((void**)&skl, g_skl);
    cudaGetSymbolAddress((void**)&cvh, g_cvh);  cudaGetSymbolAddress((void**)&cvl, g_cvl);

    cudaFuncSetAttribute(attn_tc, cudaFuncAttributeMaxDynamicSharedMemorySize,
                         ATT_SMEM_BYTES);
    cudaFuncSetAttribute(gemm_hmma, cudaFuncAttributeMaxDynamicSharedMemorySize,
                         GEMM_SMEM);

    // ---- input/weight splits ----
    split_bf16<<<MAT / 4 / 256, 256>>>(in_mean, xmh, xml, MAT / 4);
    split_bf16<<<MAT / 4 / 256, 256>>>(in_cov,  xch, xcl, MAT / 4);
    split_w8<<<dim3(WSZ / 4 / 256, 8), 256>>>(W[0], W[1], W[2], W[3],
                                              W[4], W[5], W[6], W[7], wh, wl);

    dim3 gg2(MROWS / 128, 2, 2);

    // ---- projections: 3 paired launches ----
    // mq (z=0) + mk (z=1): same A (in_mean), x3, bf16 hi+lo out
    gemm_hmma<<<gg2, 256, GEMM_SMEM>>>(xmh, xml, xmh, xml,
                                       wh + 0*WSZ, wl + 0*WSZ, wh + 1*WSZ, wl + 1*WSZ,
                                       bia[0], bia[1], nullptr, nullptr,
                                       mqh, mql, mkh, mkl, 0, 0, 1, 1);
    // sq (z=0) + sk (z=1): same A (in_cov), x3, ep=2
    gemm_hmma<<<gg2, 256, GEMM_SMEM>>>(xch, xcl, xch, xcl,
                                       wh + 3*WSZ, wl + 3*WSZ, wh + 4*WSZ, wl + 4*WSZ,
                                       bia[3], bia[4], nullptr, nullptr,
                                       sqh, sql, skh, skl, 2, 2, 1, 1);
    // mv (z=0, A=in_mean, ep=0) + cv (z=1, A=in_cov, ep=1): x1, hi-only out
    gemm_hmma<<<gg2, 256, GEMM_SMEM>>>(xmh, xml, xch, xcl,
                                       wh + 2*WSZ, wl + 2*WSZ, wh + 5*WSZ, wl + 5*WSZ,
                                       bia[2], bia[5], nullptr, nullptr,
                                       mvh, mvl, cvh, cvl, 0, 1, 2, 0);

    // ---- row scalars ----
    rowsum_kernel<<<NROW / 8, 256>>>(mqh, mql, sqh, sql, aq);
    rowsum_kernel<<<NROW / 8, 256>>>(mkh, mkl, skh, skl, ak);

    // ---- tensor-core attention ----
    attn_tc<<<dim3(SS / 64, NH, BB), 256, ATT_SMEM_BYTES>>>(mask, out + 2 * (size_t)MAT);

    // ---- output denses: one paired launch (dm + dc), x1, fp32 out ----
    gemm_hmma<<<gg2, 256, GEMM_SMEM>>>(cmh, cml, cch, ccl,
                                       wh + 6*WSZ, wl + 6*WSZ, wh + 7*WSZ, wl + 7*WSZ,
                                       bia[6], bia[7], dm, dc,
                                       nullptr, nullptr, nullptr, nullptr, 0, 0, 0, 0);

    // ---- residual + layernorm ----
    ln_kernel<<<MROWS / 8, 256>>>(dm, in_mean, lw, lb, out);
    ln_kernel<<<MROWS / 8, 256>>>(dc, in_cov,  lw, lb, out + (size_t)MAT);
}

// round 16
// speedup vs baseline: 1.1270x; 1.0272x over previous
#include <cuda_runtime.h>
#include <cuda_bf16.h>
#include <stdint.h>
#include <math.h>

// ---------------------------------------------------------------------------
// Problem constants
// ---------------------------------------------------------------------------
#define BB   64
#define SS   512
#define HID  256
#define NH   4
#define DH   64
#define MROWS (BB*SS)            // 32768
#define MAT   (MROWS*HID)        // 8388608
#define NROW  (BB*NH*SS)         // 131072
#define WSZ   (HID*HID)          // 65536

// ---------------------------------------------------------------------------
// Scratch (device globals; no allocation allowed)
// ---------------------------------------------------------------------------
__device__ float g_dm[MAT];
__device__ float g_dc[MAT];
__device__ float g_aq[NROW];
__device__ float g_ak[NROW];
__device__ __nv_bfloat16 g_xmh[MAT], g_xml[MAT];
__device__ __nv_bfloat16 g_xch[MAT], g_xcl[MAT];
__device__ __nv_bfloat16 g_cmh[MAT], g_cml[MAT];
__device__ __nv_bfloat16 g_cch[MAT], g_ccl[MAT];
__device__ __nv_bfloat16 g_wh[8*WSZ], g_wl[8*WSZ];
__device__ __nv_bfloat16 g_mqh[MAT], g_mql[MAT];
__device__ __nv_bfloat16 g_mkh[MAT], g_mkl[MAT];
__device__ __nv_bfloat16 g_mvh[MAT], g_mvl[MAT];
__device__ __nv_bfloat16 g_sqh[MAT], g_sql[MAT];
__device__ __nv_bfloat16 g_skh[MAT], g_skl[MAT];
__device__ __nv_bfloat16 g_cvh[MAT], g_cvl[MAT];

// ---------------------------------------------------------------------------
// Helpers
// ---------------------------------------------------------------------------
__device__ __forceinline__ uint32_t smem_u32(const void* p) {
    uint32_t a;
    asm("{ .reg .u64 t; cvta.to.shared.u64 t, %1; cvt.u32.u64 %0, t; }"
        : "=r"(a) : "l"(p));
    return a;
}

#define LDSM_X4(d, addr) \
    asm volatile("ldmatrix.sync.aligned.m8n8.x4.shared.b16 {%0,%1,%2,%3}, [%4];" \
        : "=r"((d)[0]), "=r"((d)[1]), "=r"((d)[2]), "=r"((d)[3]) : "r"(addr))

#define LDSM_X4_T(d, addr) \
    asm volatile("ldmatrix.sync.aligned.m8n8.x4.trans.shared.b16 {%0,%1,%2,%3}, [%4];" \
        : "=r"((d)[0]), "=r"((d)[1]), "=r"((d)[2]), "=r"((d)[3]) : "r"(addr))

#define MMA_BF16(c, a, b) \
    asm volatile("mma.sync.aligned.m16n8k16.row.col.f32.bf16.bf16.f32 " \
        "{%0,%1,%2,%3}, {%4,%5,%6,%7}, {%8,%9}, {%0,%1,%2,%3};" \
        : "+f"((c)[0]), "+f"((c)[1]), "+f"((c)[2]), "+f"((c)[3]) \
        : "r"((a)[0]), "r"((a)[1]), "r"((a)[2]), "r"((a)[3]), \
          "r"((b)[0]), "r"((b)[1]))

__device__ __forceinline__ void cp16(uint32_t saddr, const void* g) {
    asm volatile("cp.async.cg.shared.global [%0], [%1], 16;" :: "r"(saddr), "l"(g));
}
#define CP_COMMIT() asm volatile("cp.async.commit_group;")
template<int N> __device__ __forceinline__ void cp_wait() {
    asm volatile("cp.async.wait_group %0;" :: "n"(N));
}

__device__ __forceinline__ uint32_t packh(float x, float y) {
    __nv_bfloat162 r; r.x = __float2bfloat16(x); r.y = __float2bfloat16(y);
    return *(uint32_t*)&r;
}
__device__ __forceinline__ uint32_t packl(float x, float y, uint32_t hp) {
    __nv_bfloat162 h = *(__nv_bfloat162*)&hp;
    __nv_bfloat162 r;
    r.x = __float2bfloat16(x - __bfloat162float(h.x));
    r.y = __float2bfloat16(y - __bfloat162float(h.y));
    return *(uint32_t*)&r;
}

// Fast exp (FFMA pipe). |rel err| ~3e-6.
__device__ __forceinline__ float fexp(float x) {
    x = fmaxf(fminf(x, 80.f), -87.f);
    float y = x * 1.4426950408889634f;
    int   i = __float2int_rn(y);
    float f = y - (float)i;
    float p = 1.3333558146e-3f;
    p = fmaf(p, f, 9.6181291918e-3f);
    p = fmaf(p, f, 5.5504108664e-2f);
    p = fmaf(p, f, 2.4022650696e-1f);
    p = fmaf(p, f, 6.9314718056e-1f);
    p = fmaf(p, f, 1.0f);
    return __int_as_float(__float_as_int(p) + (i << 23));
}

// ---------------------------------------------------------------------------
// fp32 -> bf16 hi/lo splits (inputs merged: y selects mean/cov)
// ---------------------------------------------------------------------------
__global__ __launch_bounds__(256)
void split_x2(const float* __restrict__ x0, const float* __restrict__ x1,
              __nv_bfloat16* __restrict__ h0p, __nv_bfloat16* __restrict__ l0p,
              __nv_bfloat16* __restrict__ h1p, __nv_bfloat16* __restrict__ l1p)
{
    const int z = blockIdx.y;
    const float* x = z ? x1 : x0;
    __nv_bfloat16* hi = z ? h1p : h0p;
    __nv_bfloat16* lo = z ? l1p : l0p;
    int i = blockIdx.x * 256 + threadIdx.x;
    float4 v = ((const float4*)x)[i];
    uint32_t h0 = packh(v.x, v.y), h1 = packh(v.z, v.w);
    ((uint32_t*)hi)[i * 2]     = h0;
    ((uint32_t*)hi)[i * 2 + 1] = h1;
    ((uint32_t*)lo)[i * 2]     = packl(v.x, v.y, h0);
    ((uint32_t*)lo)[i * 2 + 1] = packl(v.z, v.w, h1);
}

__global__ __launch_bounds__(256)
void split_w8(const float* __restrict__ w0, const float* __restrict__ w1,
              const float* __restrict__ w2, const float* __restrict__ w3,
              const float* __restrict__ w4, const float* __restrict__ w5,
              const float* __restrict__ w6, const float* __restrict__ w7,
              __nv_bfloat16* __restrict__ hi, __nv_bfloat16* __restrict__ lo)
{
    const float* ws[8] = {w0, w1, w2, w3, w4, w5, w6, w7};
    const int z = blockIdx.y;
    const float* x = ws[z];
    int i = blockIdx.x * 256 + threadIdx.x;
    float4 v = ((const float4*)x)[i];
    uint32_t h0 = packh(v.x, v.y), h1 = packh(v.z, v.w);
    size_t o = (size_t)z * WSZ / 4 + i;
    ((uint32_t*)hi)[o * 2]     = h0;
    ((uint32_t*)hi)[o * 2 + 1] = h1;
    ((uint32_t*)lo)[o * 2]     = packl(v.x, v.y, h0);
    ((uint32_t*)lo)[o * 2 + 1] = packl(v.z, v.w, h1);
}

// ---------------------------------------------------------------------------
// HMMA GEMM, fully paired via blockIdx.z
// ---------------------------------------------------------------------------
#define SSTR 40
#define GEMM_SMEM (8 * 128 * SSTR * 2)

__global__ __launch_bounds__(256)
void gemm_hmma(const __nv_bfloat16* __restrict__ AhA, const __nv_bfloat16* __restrict__ AlA,
               const __nv_bfloat16* __restrict__ AhB, const __nv_bfloat16* __restrict__ AlB,
               const __nv_bfloat16* __restrict__ BhA, const __nv_bfloat16* __restrict__ BlA,
               const __nv_bfloat16* __restrict__ BhB, const __nv_bfloat16* __restrict__ BlB,
               const float* __restrict__ biasA, const float* __restrict__ biasB,
               float* __restrict__ YA, float* __restrict__ YB,
               __nv_bfloat16* __restrict__ YhA, __nv_bfloat16* __restrict__ YlA,
               __nv_bfloat16* __restrict__ YhB, __nv_bfloat16* __restrict__ YlB,
               int epA, int epB, int obf, int x3)
{
    extern __shared__ __align__(16) __nv_bfloat16 gsm[];

    const int z = blockIdx.z;
    const __nv_bfloat16* Ah = z ? AhB : AhA;
    const __nv_bfloat16* Al = z ? AlB : AlA;
    const __nv_bfloat16* Bh = z ? BhB : BhA;
    const __nv_bfloat16* Bl = z ? BlB : BlA;
    const float* bias = z ? biasB : biasA;
    float* Y = z ? YB : YA;
    __nv_bfloat16* Yh = z ? YhB : YhA;
    __nv_bfloat16* Yl = z ? YlB : YlA;
    const int ep = z ? epB : epA;

    const int tid  = threadIdx.x;
    const int wid  = tid >> 5;
    const int lane = tid & 31;
    const int m0   = blockIdx.x * 128;
    const int n0   = blockIdx.y * 128;
    const int wm   = (wid & 1) * 64;
    const int wn   = (wid >> 1) * 32;

#define SA(bd, hl) (gsm + ((bd) * 2 + (hl)) * (128 * SSTR))
#define SB(bd, hl) (gsm + (4 + (bd) * 2 + (hl)) * (128 * SSTR))

    float c[4][4][4];
#pragma unroll
    for (int mi = 0; mi < 4; mi++)
#pragma unroll
        for (int ni = 0; ni < 4; ni++)
#pragma unroll
            for (int e = 0; e < 4; e++) c[mi][ni][e] = 0.f;

    auto issue = [&](int kc, int bd) {
#pragma unroll
        for (int u = 0; u < 2; u++) {
            int idx = u * 256 + tid;
            int row = idx >> 2;
            int f4  = idx & 3;
            int soff = row * SSTR + f4 * 8;
            const size_t ga = (size_t)(m0 + row) * 256 + kc * 32 + f4 * 8;
            const size_t gb = (size_t)(n0 + row) * 256 + kc * 32 + f4 * 8;
            cp16(smem_u32(SA(bd, 0) + soff), Ah + ga);
            cp16(smem_u32(SB(bd, 0) + soff), Bh + gb);
            if (x3) {
                cp16(smem_u32(SA(bd, 1) + soff), Al + ga);
                cp16(smem_u32(SB(bd, 1) + soff), Bl + gb);
            }
        }
        CP_COMMIT();
    };

    issue(0, 0);
    for (int kc = 0; kc < 8; kc++) {
        const int cur = kc & 1;
        if (kc < 7) { issue(kc + 1, cur ^ 1); cp_wait<1>(); }
        else        { cp_wait<0>(); }
        __syncthreads();

#pragma unroll
        for (int ks = 0; ks < 2; ks++) {
            const int kb = ks * 16;
            uint32_t ah[4][4], al[4][4];
            {
                const int r  = wm + (lane & 15);
                const int kk = kb + (lane >> 4) * 8;
#pragma unroll
                for (int mi = 0; mi < 4; mi++) {
                    LDSM_X4(ah[mi], smem_u32(SA(cur, 0) + (r + mi * 16) * SSTR + kk));
                    if (x3) LDSM_X4(al[mi], smem_u32(SA(cur, 1) + (r + mi * 16) * SSTR + kk));
                }
            }
            uint32_t bh[2][4], bl[2][4];
            {
                const int nr = (lane & 7) + ((lane >> 4) & 1) * 8;
                const int kk = kb + ((lane >> 3) & 1) * 8;
#pragma unroll
                for (int ng = 0; ng < 2; ng++) {
                    LDSM_X4(bh[ng], smem_u32(SB(cur, 0) + (wn + ng * 16 + nr) * SSTR + kk));
                    if (x3) LDSM_X4(bl[ng], smem_u32(SB(cur, 1) + (wn + ng * 16 + nr) * SSTR + kk));
                }
            }
#pragma unroll
            for (int mi = 0; mi < 4; mi++)
#pragma unroll
                for (int ni = 0; ni < 4; ni++) {
                    uint32_t* bH = &bh[ni >> 1][(ni & 1) * 2];
                    MMA_BF16(c[mi][ni], ah[mi], bH);
                    if (x3) {
                        uint32_t* bL = &bl[ni >> 1][(ni & 1) * 2];
                        MMA_BF16(c[mi][ni], ah[mi], bL);
                        MMA_BF16(c[mi][ni], al[mi], bH);
                    }
                }
        }
        __syncthreads();
    }

    const int mrow = m0 + wm + (lane >> 2);
    const int ncol = n0 + wn + 2 * (lane & 3);
#pragma unroll
    for (int mi = 0; mi < 4; mi++) {
#pragma unroll
        for (int ni = 0; ni < 4; ni++) {
            const int col = ncol + ni * 8;
            float v[4];
#pragma unroll
            for (int e = 0; e < 4; e++) {
                float t = c[mi][ni][e] + bias[col + (e & 1)];
                if (ep >= 1) t = (t > 0.f) ? (t + 1.f) : __expf(t);
                if (ep == 2) t = sqrtf(fmaxf(t, 1e-24f));
                v[e] = t;
            }
            const size_t i0 = (size_t)(mrow + mi * 16) * 256 + col;
            const size_t i1 = (size_t)(mrow + mi * 16 + 8) * 256 + col;
            if (obf) {
                uint32_t h0 = packh(v[0], v[1]), h1 = packh(v[2], v[3]);
                *(uint32_t*)&Yh[i0] = h0;
                *(uint32_t*)&Yh[i1] = h1;
                if (obf == 1) {
                    *(uint32_t*)&Yl[i0] = packl(v[0], v[1], h0);
                    *(uint32_t*)&Yl[i1] = packl(v[2], v[3], h1);
                }
            } else {
                *(float2*)(Y + i0) = make_float2(v[0], v[1]);
                *(float2*)(Y + i1) = make_float2(v[2], v[3]);
            }
        }
    }
#undef SA
#undef SB
}

// ---------------------------------------------------------------------------
// Row scalars (merged: y=0 -> q side, y=1 -> k side)
// ---------------------------------------------------------------------------
__global__ __launch_bounds__(256)
void rowsum2(float* __restrict__ Aq, float* __restrict__ Ak)
{
    const int z    = blockIdx.y;
    const __nv_bfloat16* Mh = z ? g_mkh : g_mqh;
    const __nv_bfloat16* Ml = z ? g_mkl : g_mql;
    const __nv_bfloat16* Sh = z ? g_skh : g_sqh;
    const __nv_bfloat16* Sl = z ? g_skl : g_sql;
    float* A = z ? Ak : Aq;

    const int w    = (blockIdx.x * blockDim.x + threadIdx.x) >> 5;
    const int lane = threadIdx.x & 31;
    const int s  = w & 511;
    const int bh = w >> 9;
    const int b  = bh >> 2, h = bh & 3;
    const size_t base = ((size_t)(b * 512 + s) * 256) + h * 64 + lane * 2;
    float2 mh = __bfloat1622float2(*(const __nv_bfloat162*)&Mh[base]);
    float2 ml = __bfloat1622float2(*(const __nv_bfloat162*)&Ml[base]);
    float2 sh = __bfloat1622float2(*(const __nv_bfloat162*)&Sh[base]);
    float2 sl = __bfloat1622float2(*(const __nv_bfloat162*)&Sl[base]);
    float m0 = mh.x + ml.x, m1 = mh.y + ml.y;
    float s0 = sh.x + sl.x, s1 = sh.y + sl.y;
    float sum = m0 * m0 + m1 * m1 + s0 * s0 + s1 * s1;
#pragma unroll
    for (int o = 16; o; o >>= 1) sum += __shfl_xor_sync(~0u, sum, o);
    if (!lane) A[w] = sum;
}

// ---------------------------------------------------------------------------
// Tensor-core attention. Change vs R15: probs gmem write folded into the
// phase-C P-pack loop (standalone normalize pass removed).
// ---------------------------------------------------------------------------
#define SC_STR 516
#define QS 136
#define VS 72
#define BFREG_BYTES 69632
#define ATT_SMEM_BYTES ((640 + 64*SC_STR) * 4 + BFREG_BYTES)   // 204288

__global__ __launch_bounds__(256)
void attn_tc(const float* __restrict__ mask, float* __restrict__ probs)
{
    extern __shared__ __align__(16) float sm[];
    float* aqs   = sm;
    float* aks   = sm + 64;
    float* invzs = sm + 576;
    float* Ssc   = sm + 640;
    __nv_bfloat16* bfr = (__nv_bfloat16*)(sm + 640 + 64 * SC_STR);
    __nv_bfloat16* Khi0 = bfr;
    __nv_bfloat16* Klo0 = bfr + 64 * QS;
    __nv_bfloat16* Khi1 = bfr + 2 * 64 * QS;
    __nv_bfloat16* Klo1 = bfr + 3 * 64 * QS;
    __nv_bfloat16* Phi  = bfr;
    __nv_bfloat16* P2hi = bfr + 64 * VS;
    __nv_bfloat16* Vmh0 = bfr + 2 * 64 * VS;
    __nv_bfloat16* Vch0 = bfr + 3 * 64 * VS;
    __nv_bfloat16* Vmh1 = bfr + 4 * 64 * VS;
    __nv_bfloat16* Vch1 = bfr + 5 * 64 * VS;

    const int tid  = threadIdx.x;
    const int wid  = tid >> 5;
    const int lane = tid & 31;
    const int g    = lane >> 2;
    const int t    = lane & 3;
    const int q0   = blockIdx.x * 64;
    const int h    = blockIdx.y;
    const int b    = blockIdx.z;
    const int wm2  = (wid & 1) * 32;
    const int wn   = (wid >> 1) * 16;

    const float* mrow = mask + ((size_t)b * 512 + q0) * 512;

    auto issueK = [&](int kt, __nv_bfloat16* KH, __nv_bfloat16* KL) {
#pragma unroll
        for (int u = 0; u < 4; u++) {
            int idx = u * 256 + tid;
            int row = idx >> 4;
            int c8  = (idx & 15) * 8;
            const size_t src = ((size_t)(b * 512 + kt * 64 + row) * 256) + h * 64
                             + (c8 < 64 ? c8 : c8 - 64);
            const __nv_bfloat16* ph = (c8 < 64) ? g_mkh : g_skh;
            const __nv_bfloat16* pl = (c8 < 64) ? g_mkl : g_skl;
            cp16(smem_u32(&KH[row * QS + c8]), ph + src);
            cp16(smem_u32(&KL[row * QS + c8]), pl + src);
        }
        CP_COMMIT();
    };
    auto issueV = [&](int kt, __nv_bfloat16* VM, __nv_bfloat16* VC) {
#pragma unroll
        for (int u = 0; u < 2; u++) {
            int idx = u * 256 + tid;
            int row = idx >> 3;
            int d8  = (idx & 7) * 8;
            const size_t src = ((size_t)(b * 512 + kt * 64 + row) * 256) + h * 64 + d8;
            cp16(smem_u32(&VM[row * VS + d8]), g_mvh + src);
            cp16(smem_u32(&VC[row * VS + d8]), g_cvh + src);
        }
        CP_COMMIT();
    };

    if (tid < 64) aqs[tid] = g_aq[(b * 4 + h) * 512 + q0 + tid];
    aks[tid]       = g_ak[(b * 4 + h) * 512 + tid];
    aks[tid + 256] = g_ak[(b * 4 + h) * 512 + 256 + tid];

    issueK(0, Khi0, Klo0);

    // ---- stage Q in buf1 ----
#pragma unroll
    for (int u = 0; u < 4; u++) {
        int idx = u * 256 + tid;
        int row = idx >> 4;
        int c8  = (idx & 15) * 8;
        const size_t src = ((size_t)(b * 512 + q0 + row) * 256) + h * 64
                         + (c8 < 64 ? c8 : c8 - 64);
        const __nv_bfloat16* ph = (c8 < 64) ? g_mqh : g_sqh;
        const __nv_bfloat16* pl = (c8 < 64) ? g_mql : g_sql;
        *(uint4*)&Khi1[row * QS + c8] = *(const uint4*)(ph + src);
        *(uint4*)&Klo1[row * QS + c8] = *(const uint4*)(pl + src);
    }
    __syncthreads();

    // ---- hoist Q fragments to registers (kt-invariant) ----
    uint32_t qfh[8][2][4], qfl[8][2][4];
    {
        const int ar = wm2 + (lane & 15);
#pragma unroll
        for (int ks = 0; ks < 8; ks++) {
            const int akk = ks * 16 + (lane >> 4) * 8;
#pragma unroll
            for (int mi = 0; mi < 2; mi++) {
                LDSM_X4(qfh[ks][mi], smem_u32(&Khi1[(ar + mi * 16) * QS + akk]));
                LDSM_X4(qfl[ks][mi], smem_u32(&Klo1[(ar + mi * 16) * QS + akk]));
            }
        }
    }

    // ================= Phase A =================
    for (int kt = 0; kt < 8; kt++) {
        cp_wait<0>();
        __syncthreads();
        __nv_bfloat16* KH = (kt & 1) ? Khi1 : Khi0;
        __nv_bfloat16* KL = (kt & 1) ? Klo1 : Klo0;
        if (kt < 7) issueK(kt + 1, (kt & 1) ? Khi0 : Khi1, (kt & 1) ? Klo0 : Klo1);

        float acc[2][2][4], acl[2][2][4], acm[2][2][4];
#pragma unroll
        for (int mi = 0; mi < 2; mi++)
#pragma unroll
            for (int ni = 0; ni < 2; ni++)
#pragma unroll
                for (int e = 0; e < 4; e++) {
                    acc[mi][ni][e] = 0.f; acl[mi][ni][e] = 0.f; acm[mi][ni][e] = 0.f;
                }

#pragma unroll
        for (int ks = 0; ks < 8; ks++) {
            uint32_t bh[4], bl[4];
            const int nr  = (lane & 7) + ((lane >> 4) & 1) * 8;
            const int kk2 = ks * 16 + ((lane >> 3) & 1) * 8;
            LDSM_X4(bh, smem_u32(&KH[(wn + nr) * QS + kk2]));
            LDSM_X4(bl, smem_u32(&KL[(wn + nr) * QS + kk2]));
#pragma unroll
            for (int mi = 0; mi < 2; mi++)
#pragma unroll
                for (int ni = 0; ni < 2; ni++) {
                    MMA_BF16(acc[mi][ni], qfh[ks][mi], (&bh[ni * 2]));
                    MMA_BF16(acl[mi][ni], qfh[ks][mi], (&bl[ni * 2]));
                    MMA_BF16(acm[mi][ni], qfl[ks][mi], (&bh[ni * 2]));
                }
        }

        // epilogue: dist -> e into Ssc (mask direct from gmem)
#pragma unroll
        for (int mi = 0; mi < 2; mi++) {
            const int i0 = wm2 + mi * 16 + g;
#pragma unroll
            for (int ni = 0; ni < 2; ni++) {
                const int j = kt * 64 + wn + ni * 8 + 2 * t;
                const float akj0 = aks[j], akj1 = aks[j + 1];
                float2 m0 = *(const float2*)&mrow[(size_t)i0 * 512 + j];
                float2 m1 = *(const float2*)&mrow[(size_t)(i0 + 8) * 512 + j];
                float s00 = acc[mi][ni][0] + acl[mi][ni][0] + acm[mi][ni][0];
                float s01 = acc[mi][ni][1] + acl[mi][ni][1] + acm[mi][ni][1];
                float s10 = acc[mi][ni][2] + acl[mi][ni][2] + acm[mi][ni][2];
                float s11 = acc[mi][ni][3] + acl[mi][ni][3] + acm[mi][ni][3];
                float d00 = aqs[i0]     + akj0 - 2.f * s00;
                float d01 = aqs[i0]     + akj1 - 2.f * s01;
                float d10 = aqs[i0 + 8] + akj0 - 2.f * s10;
                float d11 = aqs[i0 + 8] + akj1 - 2.f * s11;
                *(float2*)&Ssc[i0 * SC_STR + j] =
                    make_float2(fexp(-d00) * 0.125f + m0.x, fexp(-d01) * 0.125f + m0.y);
                *(float2*)&Ssc[(i0 + 8) * SC_STR + j] =
                    make_float2(fexp(-d10) * 0.125f + m1.x, fexp(-d11) * 0.125f + m1.y);
            }
        }
    }
    __syncthreads();

    // ================= Phase B: softmax stats =================
    {
        const int row = tid >> 2, sub = tid & 3;
        float m = -3.0e38f;
        for (int k = sub; k < 512; k += 4) m = fmaxf(m, Ssc[row * SC_STR + k]);
        m = fmaxf(m, __shfl_xor_sync(~0u, m, 1));
        m = fmaxf(m, __shfl_xor_sync(~0u, m, 2));
        float s = 0.f;
        for (int k = sub; k < 512; k += 4) {
            float e = fexp(Ssc[row * SC_STR + k] - m);
            Ssc[row * SC_STR + k] = e;
            s += e;
        }
        s += __shfl_xor_sync(~0u, s, 1);
        s += __shfl_xor_sync(~0u, s, 2);
        if (sub == 0) invzs[row] = 1.f / s;
    }
    __syncthreads();

    issueV(0, Vmh0, Vch0);

    // ================= Phase C: PV (probs write fused into pack loop) ======
    float am[2][2][4], ac2[2][2][4];
#pragma unroll
    for (int mi = 0; mi < 2; mi++)
#pragma unroll
        for (int ni = 0; ni < 2; ni++)
#pragma unroll
            for (int e = 0; e < 4; e++) { am[mi][ni][e] = 0.f; ac2[mi][ni][e] = 0.f; }

    const size_t pbase = (((size_t)(b * 4 + h)) * 512 + q0) * 512;

    for (int kt = 0; kt < 8; kt++) {
        if (kt > 0) __syncthreads();           // prior P/V-alt reads done
#pragma unroll
        for (int u = 0; u < 8; u++) {
            int idx = u * 256 + tid;
            int row = idx >> 5;
            int cp  = (idx & 31) * 2;
            float z = invzs[row];
            float2 p = *(const float2*)&Ssc[row * SC_STR + kt * 64 + cp];
            float px = p.x * z, py = p.y * z;
            *(float2*)(probs + pbase + (size_t)row * 512 + kt * 64 + cp) =
                make_float2(px, py);
            *(uint32_t*)&Phi[row * VS + cp]  = packh(px, py);
            *(uint32_t*)&P2hi[row * VS + cp] = packh(px * px, py * py);
        }
        cp_wait<0>();                          // V(kt) landed
        __syncthreads();                       // P + V visible
        __nv_bfloat16* VM = (kt & 1) ? Vmh1 : Vmh0;
        __nv_bfloat16* VC = (kt & 1) ? Vch1 : Vch0;
        if (kt < 7) issueV(kt + 1, (kt & 1) ? Vmh0 : Vmh1, (kt & 1) ? Vch0 : Vch1);

#pragma unroll
        for (int ks = 0; ks < 4; ks++) {
            const int s0 = ks * 16;
            uint32_t ph[2][4], qh[2][4];
            const int ar = wm2 + (lane & 15);
            const int ac = s0 + (lane >> 4) * 8;
#pragma unroll
            for (int mi = 0; mi < 2; mi++) {
                LDSM_X4(ph[mi], smem_u32(&Phi [(ar + mi * 16) * VS + ac]));
                LDSM_X4(qh[mi], smem_u32(&P2hi[(ar + mi * 16) * VS + ac]));
            }
            uint32_t bmh[4], bch[4];
            const int sr = (lane & 7) + ((lane >> 3) & 1) * 8;
            const int d8 = (lane >> 4) * 8;
            const int vbase = (s0 + sr) * VS + wn + d8;
            LDSM_X4_T(bmh, smem_u32(&VM[vbase]));
            LDSM_X4_T(bch, smem_u32(&VC[vbase]));
#pragma unroll
            for (int mi = 0; mi < 2; mi++)
#pragma unroll
                for (int ni = 0; ni < 2; ni++) {
                    MMA_BF16(am[mi][ni],  ph[mi], (&bmh[ni * 2]));
                    MMA_BF16(ac2[mi][ni], qh[mi], (&bch[ni * 2]));
                }
        }
    }

    // ---- store ctx (hi only) ----
#pragma unroll
    for (int mi = 0; mi < 2; mi++) {
#pragma unroll
        for (int ni = 0; ni < 2; ni++) {
            const int row = q0 + wm2 + mi * 16 + g;
            const int col = h * 64 + wn + ni * 8 + 2 * t;
            const size_t i0 = ((size_t)(b * 512 + row)) * 256 + col;
            const size_t i1 = ((size_t)(b * 512 + row + 8)) * 256 + col;
            *(uint32_t*)&g_cmh[i0] = packh(am[mi][ni][0], am[mi][ni][1]);
            *(uint32_t*)&g_cmh[i1] = packh(am[mi][ni][2], am[mi][ni][3]);
            *(uint32_t*)&g_cch[i0] = packh(ac2[mi][ni][0], ac2[mi][ni][1]);
            *(uint32_t*)&g_cch[i1] = packh(ac2[mi][ni][2], ac2[mi][ni][3]);
        }
    }
}

// ---------------------------------------------------------------------------
// LayerNorm (merged: y=0 -> mean side, y=1 -> cov side)
// ---------------------------------------------------------------------------
__global__ __launch_bounds__(256)
void ln2(const float* __restrict__ Xm, const float* __restrict__ Xc,
         const float* __restrict__ lw, const float* __restrict__ lb,
         float* __restrict__ O0, float* __restrict__ O1)
{
    const int z = blockIdx.y;
    const float* D = z ? g_dc : g_dm;
    const float* X = z ? Xc : Xm;
    float* O = z ? O1 : O0;

    const int warp = threadIdx.x >> 5, lane = threadIdx.x & 31;
    const int r = blockIdx.x * 8 + warp;
    const size_t base = (size_t)r * 256 + lane * 8;
    float4 d0 = *(const float4*)(D + base);
    float4 d1 = *(const float4*)(D + base + 4);
    float4 x0 = *(const float4*)(X + base);
    float4 x1 = *(const float4*)(X + base + 4);
    float v[8] = {d0.x + x0.x, d0.y + x0.y, d0.z + x0.z, d0.w + x0.w,
                  d1.x + x1.x, d1.y + x1.y, d1.z + x1.z, d1.w + x1.w};
    float s1 = 0.f, s2 = 0.f;
#pragma unroll
    for (int e = 0; e < 8; e++) { s1 += v[e]; s2 += v[e] * v[e]; }
#pragma unroll
    for (int o = 16; o; o >>= 1) {
        s1 += __shfl_xor_sync(~0u, s1, o);
        s2 += __shfl_xor_sync(~0u, s2, o);
    }
    float u   = s1 * (1.f / 256.f);
    float var = fmaxf(s2 * (1.f / 256.f) - u * u, 0.f);
    float is  = rsqrtf(var + 1e-12f);
    float y[8];
#pragma unroll
    for (int e = 0; e < 8; e++)
        y[e] = fmaf(lw[lane * 8 + e], (v[e] - u) * is, lb[lane * 8 + e]);
    *(float4*)(O + base)     = make_float4(y[0], y[1], y[2], y[3]);
    *(float4*)(O + base + 4) = make_float4(y[4], y[5], y[6], y[7]);
}

// ---------------------------------------------------------------------------
// kernel_launch
// ---------------------------------------------------------------------------
extern "C" void kernel_launch(void* const* d_in, const int* in_sizes, int n_in,
                              void* d_out, int out_size)
{
    (void)in_sizes; (void)n_in; (void)out_size;
    const float* in_mean = (const float*)d_in[0];
    const float* in_cov  = (const float*)d_in[1];
    const float* mask    = (const float*)d_in[2];
    const float* W[8]    = { (const float*)d_in[3],  (const float*)d_in[5],
                             (const float*)d_in[7],  (const float*)d_in[9],
                             (const float*)d_in[11], (const float*)d_in[13],
                             (const float*)d_in[15], (const float*)d_in[17] };
    const float* bia[8]  = { (const float*)d_in[4],  (const float*)d_in[6],
                             (const float*)d_in[8],  (const float*)d_in[10],
                             (const float*)d_in[12], (const float*)d_in[14],
                             (const float*)d_in[16], (const float*)d_in[18] };
    const float* lw  = (const float*)d_in[19];
    const float* lb  = (const float*)d_in[20];
    float* out = (float*)d_out;

    float *dm, *dc, *aq, *ak;
    cudaGetSymbolAddress((void**)&dm, g_dm);
    cudaGetSymbolAddress((void**)&dc, g_dc);
    cudaGetSymbolAddress((void**)&aq, g_aq);
    cudaGetSymbolAddress((void**)&ak, g_ak);

    __nv_bfloat16 *xmh, *xml, *xch, *xcl, *cmh, *cml, *cch, *ccl, *wh, *wl;
    __nv_bfloat16 *mqh, *mql, *mkh, *mkl, *mvh, *mvl, *sqh, *sql, *skh, *skl, *cvh, *cvl;
    cudaGetSymbolAddress((void**)&xmh, g_xmh);  cudaGetSymbolAddress((void**)&xml, g_xml);
    cudaGetSymbolAddress((void**)&xch, g_xch);  cudaGetSymbolAddress((void**)&xcl, g_xcl);
    cudaGetSymbolAddress((void**)&cmh, g_cmh);  cudaGetSymbolAddress((void**)&cml, g_cml);
    cudaGetSymbolAddress((void**)&cch, g_cch);  cudaGetSymbolAddress((void**)&ccl, g_ccl);
    cudaGetSymbolAddress((void**)&wh,  g_wh);   cudaGetSymbolAddress((void**)&wl,  g_wl);
    cudaGetSymbolAddress((void**)&mqh, g_mqh);  cudaGetSymbolAddress((void**)&mql, g_mql);
    cudaGetSymbolAddress((void**)&mkh, g_mkh);  cudaGetSymbolAddress((void**)&mkl, g_mkl);
    cudaGetSymbolAddress((void**)&mvh, g_mvh);  cudaGetSymbolAddress((void**)&mvl, g_mvl);
    cudaGetSymbolAddress((void**)&sqh, g_sqh);  cudaGetSymbolAddress((void**)&sql, g_sql);
    cudaGetSymbolAddress((void**)&skh, g_skh);  cudaGetSymbolAddress((void**)&skl, g_skl);
    cudaGetSymbolAddress((void**)&cvh, g_cvh);  cudaGetSymbolAddress((void**)&cvl, g_cvl);

    cudaFuncSetAttribute(attn_tc, cudaFuncAttributeMaxDynamicSharedMemorySize,
                         ATT_SMEM_BYTES);
    cudaFuncSetAttribute(gemm_hmma, cudaFuncAttributeMaxDynamicSharedMemorySize,
                         GEMM_SMEM);

    // ---- input/weight splits (merged launches) ----
    split_x2<<<dim3(MAT / 4 / 256, 2), 256>>>(in_mean, in_cov, xmh, xml, xch, xcl);
    split_w8<<<dim3(WSZ / 4 / 256, 8), 256>>>(W[0], W[1], W[2], W[3],
                                              W[4], W[5], W[6], W[7], wh, wl);

    dim3 gg2(MROWS / 128, 2, 2);

    // ---- projections: 3 paired launches ----
    gemm_hmma<<<gg2, 256, GEMM_SMEM>>>(xmh, xml, xmh, xml,
                                       wh + 0*WSZ, wl + 0*WSZ, wh + 1*WSZ, wl + 1*WSZ,
                                       bia[0], bia[1], nullptr, nullptr,
                                       mqh, mql, mkh, mkl, 0, 0, 1, 1);
    gemm_hmma<<<gg2, 256, GEMM_SMEM>>>(xch, xcl, xch, xcl,
                                       wh + 3*WSZ, wl + 3*WSZ, wh + 4*WSZ, wl + 4*WSZ,
                                       bia[3], bia[4], nullptr, nullptr,
                                       sqh, sql, skh, skl, 2, 2, 1, 1);
    gemm_hmma<<<gg2, 256, GEMM_SMEM>>>(xmh, xml, xch, xcl,
                                       wh + 2*WSZ, wl + 2*WSZ, wh + 5*WSZ, wl + 5*WSZ,
                                       bia[2], bia[5], nullptr, nullptr,
                                       mvh, mvl, cvh, cvl, 0, 1, 2, 0);

    // ---- row scalars (merged) ----
    rowsum2<<<dim3(NROW / 8, 2), 256>>>(aq, ak);

    // ---- tensor-core attention ----
    attn_tc<<<dim3(SS / 64, NH, BB), 256, ATT_SMEM_BYTES>>>(mask, out + 2 * (size_t)MAT);

    // ---- output denses: one paired launch ----
    gemm_hmma<<<gg2, 256, GEMM_SMEM>>>(cmh, cml, cch, ccl,
                                       wh + 6*WSZ, wl + 6*WSZ, wh + 7*WSZ, wl + 7*WSZ,
                                       bia[6], bia[7], dm, dc,
                                       nullptr, nullptr, nullptr, nullptr, 0, 0, 0, 0);

    // ---- residual + layernorm (merged) ----
    ln2<<<dim3(MROWS / 8, 2), 256>>>(in_mean, in_cov, lw, lb, out, out + (size_t)MAT);
}